// round 1
// baseline (speedup 1.0000x reference)
#include <cuda_runtime.h>
#include <math.h>

// ---------------- problem constants ----------------
#define N_NODES 6000
#define F_IN    512
#define HID     64
#define H1      8
#define C_OUT   40
#define NW      188            // ceil(6000/32) words per adjacency row
#define ALPHA   0.2f
#define OUT_ADJ_OFF (N_NODES * C_OUT)   // 240000

// ---------------- device scratch (static, allocation-free) ----------------
__device__ float    g_Wh  [H1 * N_NODES * HID];      // layer1 Wh: [h][n][64]
__device__ unsigned g_adjb[N_NODES * NW];            // packed adjacency bits
__device__ float    g_h1  [N_NODES * (H1 * HID)];    // layer1 output (concat, post-ELU)
__device__ float    g_Wh2 [N_NODES * C_OUT];         // layer2 Wh

__device__ float g_Ssrc[H1 * N_NODES], g_Ei[H1 * N_NODES], g_Fi[H1 * N_NODES];
__device__ float g_Stgt[H1 * N_NODES], g_Ej[H1 * N_NODES], g_Fj[H1 * N_NODES];
__device__ float g_S2src[N_NODES], g_E2i[N_NODES], g_F2i[N_NODES];
__device__ float g_S2tgt[N_NODES], g_E2j[N_NODES], g_F2j[N_NODES];

// ---------------- kernel 1: pack adjacency bits + copy adj to output ----------------
__global__ void pack_adj_kernel(const int* __restrict__ adj,
                                float* __restrict__ outf, long out_size) {
    int gtid = blockIdx.x * blockDim.x + threadIdx.x;
    int warp = gtid >> 5, lane = gtid & 31;
    int row = warp / NW, wj = warp % NW;
    int j = wj * 32 + lane;
    int v = 0;
    if (j < N_NODES) {
        long idx = (long)row * N_NODES + j;
        v = adj[idx];
        long oi = (long)OUT_ADJ_OFF + idx;
        if (oi < out_size) outf[oi] = (float)v;
    }
    unsigned bits = __ballot_sync(0xFFFFFFFFu, v != 0);
    if (lane == 0) g_adjb[row * NW + wj] = bits;
}

// ---------------- kernel 2: Wh = x @ W1[h]  (per-head 6000x512x64) ----------------
// block: 128 threads, tile 64 rows x 64 cols (one head), thread tile 8x4
__global__ void __launch_bounds__(128) gemm1_kernel(const float* __restrict__ x,
                                                    const float* __restrict__ W1) {
    __shared__ float As[16][64];      // [k][row]
    __shared__ float Bs[16 * 64];     // [k][col] natural layout
    int h  = blockIdx.y;
    int i0 = blockIdx.x * 64;
    int tid = threadIdx.x;
    int tc = tid & 15, tr = tid >> 4;     // 16 col-groups x4, 8 row-groups x8
    const float* Bsrc = W1 + (size_t)h * F_IN * HID;
    float acc[8][4];
    #pragma unroll
    for (int r = 0; r < 8; r++)
        #pragma unroll
        for (int c = 0; c < 4; c++) acc[r][c] = 0.f;

    for (int k0 = 0; k0 < F_IN; k0 += 16) {
        int r  = tid >> 2;
        int kc = (tid & 3) * 4;
        #pragma unroll
        for (int rr = 0; rr < 2; rr++) {
            int row = r + rr * 32;
            float4 v = make_float4(0.f, 0.f, 0.f, 0.f);
            if (i0 + row < N_NODES)
                v = *(const float4*)&x[(size_t)(i0 + row) * F_IN + k0 + kc];
            As[kc + 0][row] = v.x; As[kc + 1][row] = v.y;
            As[kc + 2][row] = v.z; As[kc + 3][row] = v.w;
        }
        const float4* bs = (const float4*)(Bsrc + (size_t)k0 * HID);
        float4* bd = (float4*)Bs;
        bd[tid]       = bs[tid];
        bd[tid + 128] = bs[tid + 128];
        __syncthreads();
        #pragma unroll
        for (int kk = 0; kk < 16; kk++) {
            float a[8], b[4];
            *(float4*)&a[0] = *(float4*)&As[kk][tr * 8];
            *(float4*)&a[4] = *(float4*)&As[kk][tr * 8 + 4];
            *(float4*)&b[0] = *(float4*)&Bs[kk * 64 + tc * 4];
            #pragma unroll
            for (int rr = 0; rr < 8; rr++)
                #pragma unroll
                for (int cc = 0; cc < 4; cc++)
                    acc[rr][cc] += a[rr] * b[cc];
        }
        __syncthreads();
    }
    #pragma unroll
    for (int rr = 0; rr < 8; rr++) {
        int row = i0 + tr * 8 + rr;
        if (row < N_NODES)
            *(float4*)&g_Wh[((size_t)h * N_NODES + row) * HID + tc * 4] = *(float4*)&acc[rr][0];
    }
}

// ---------------- kernel 3: per-node scores + exponentials (layer 1) ----------------
__global__ void scores1_kernel(const float* __restrict__ a_src,
                               const float* __restrict__ a_tgt) {
    int gw = (blockIdx.x * blockDim.x + threadIdx.x) >> 5;
    int lane = threadIdx.x & 31;
    if (gw >= H1 * N_NODES) return;
    int h = gw / N_NODES, n = gw % N_NODES;
    const float* wh = &g_Wh[((size_t)h * N_NODES + n) * HID];
    float w1 = wh[lane], w2 = wh[lane + 32];
    float ss = w1 * a_src[h * HID + lane] + w2 * a_src[h * HID + lane + 32];
    float st = w1 * a_tgt[h * HID + lane] + w2 * a_tgt[h * HID + lane + 32];
    #pragma unroll
    for (int o = 16; o > 0; o >>= 1) {
        ss += __shfl_xor_sync(0xFFFFFFFFu, ss, o);
        st += __shfl_xor_sync(0xFFFFFFFFu, st, o);
    }
    if (lane == 0) {
        g_Ssrc[gw] = ss; g_Ei[gw] = expf(ss); g_Fi[gw] = expf(ALPHA * ss);
        g_Stgt[gw] = st; g_Ej[gw] = expf(st); g_Fj[gw] = expf(ALPHA * st);
    }
}

// ---------------- kernel 4: fused masked-softmax AV, layer 1 ----------------
// block: 128 threads. Tile: 128 rows(i) x 64 dims, loop j in tiles of 32.
// Build phase: thread t owns local row t -> builds w column + running Z.
// Compute phase: thread (rg,dg) owns 8 rows x 8 dims, classic register tile.
#define TI 128
#define TJ 32

__global__ void __launch_bounds__(128) av1_kernel() {
    __shared__ float w_s [TJ * TI];       // 16 KB  [jj][row]
    __shared__ float wh_s[TJ * HID];      // 8 KB   [jj][dim]
    __shared__ float st_s[TJ], ej_s[TJ], fj_s[TJ];
    __shared__ float z_s[TI];

    int h  = blockIdx.y;
    int i0 = blockIdx.x * TI;
    int tid = threadIdx.x;
    int dg = tid & 7, rg = tid >> 3;

    int myrow = i0 + tid;
    bool rvalid = myrow < N_NODES;
    float Ei = 0.f, Fi = 0.f, ssrc = 0.f;
    if (rvalid) {
        Ei   = g_Ei  [h * N_NODES + myrow];
        Fi   = g_Fi  [h * N_NODES + myrow];
        ssrc = g_Ssrc[h * N_NODES + myrow];
    }
    const unsigned* adjrow = &g_adjb[(size_t)(rvalid ? myrow : 0) * NW];
    const float* whbase = &g_Wh[(size_t)h * N_NODES * HID];

    float acc[8][8];
    #pragma unroll
    for (int r = 0; r < 8; r++)
        #pragma unroll
        for (int d = 0; d < 8; d++) acc[r][d] = 0.f;
    float zacc = 0.f;

    for (int j0 = 0; j0 < N_NODES; j0 += TJ) {
        // ---- stage Wh tile (zero-fill tail to avoid NaN poisoning) ----
        #pragma unroll
        for (int r = 0; r < 4; r++) {
            int lin  = r * 512 + tid * 4;
            int jrow = lin >> 6;
            float4 v = make_float4(0.f, 0.f, 0.f, 0.f);
            if (j0 + jrow < N_NODES)
                v = *(const float4*)&whbase[(size_t)(j0 + jrow) * HID + (lin & 63)];
            *(float4*)&wh_s[lin] = v;
        }
        if (tid < TJ) {
            int j = j0 + tid;
            bool jv = j < N_NODES;
            st_s[tid] = jv ? g_Stgt[h * N_NODES + j] : 0.f;
            ej_s[tid] = jv ? g_Ej  [h * N_NODES + j] : 0.f;
            fj_s[tid] = jv ? g_Fj  [h * N_NODES + j] : 0.f;
        }
        __syncthreads();

        // ---- build w column for my row (branchless) ----
        {
            unsigned bits = rvalid ? adjrow[j0 >> 5] : 0u;
            #pragma unroll 8
            for (int k = 0; k < TJ; k++) {
                float m = (float)((bits >> k) & 1u);
                bool cond = (ssrc + st_s[k]) > 0.f;
                float w = m * (cond ? Ei * ej_s[k] : Fi * fj_s[k]);
                w_s[k * TI + tid] = w;
                zacc += w;
            }
        }
        __syncthreads();

        // ---- compute: acc += w_tile^T-slice x wh_tile ----
        #pragma unroll 4
        for (int jj = 0; jj < TJ; jj++) {
            float a[8], b[8];
            *(float4*)&a[0] = *(float4*)&w_s[jj * TI + rg * 8];
            *(float4*)&a[4] = *(float4*)&w_s[jj * TI + rg * 8 + 4];
            *(float4*)&b[0] = *(float4*)&wh_s[jj * HID + dg * 8];
            *(float4*)&b[4] = *(float4*)&wh_s[jj * HID + dg * 8 + 4];
            #pragma unroll
            for (int r = 0; r < 8; r++)
                #pragma unroll
                for (int d = 0; d < 8; d++)
                    acc[r][d] += a[r] * b[d];
        }
        __syncthreads();
    }

    z_s[tid] = zacc;
    __syncthreads();

    #pragma unroll
    for (int r = 0; r < 8; r++) {
        int iloc = rg * 8 + r;
        int row = i0 + iloc;
        if (row < N_NODES) {
            float invZ = 1.0f / z_s[iloc];
            float o[8];
            #pragma unroll
            for (int d = 0; d < 8; d++) {
                float v = acc[r][d] * invZ;
                o[d] = v > 0.f ? v : expm1f(v);   // ELU
            }
            float* dst = &g_h1[(size_t)row * (H1 * HID) + h * HID + dg * 8];
            *(float4*)&dst[0] = *(float4*)&o[0];
            *(float4*)&dst[4] = *(float4*)&o[4];
        }
    }
}

// ---------------- kernel 5: Wh2 = h1 @ W2  (6000x512x40) ----------------
// block: 128 threads, tile 128 rows x 40 cols, thread tile 8 rows x 5 cols
__global__ void __launch_bounds__(128) gemm2_kernel(const float* __restrict__ W2) {
    __shared__ float As[16][128];     // [k][row]
    __shared__ float Bs[16 * 40];     // [k][col]
    int i0 = blockIdx.x * 128;
    int tid = threadIdx.x;
    int cg = tid & 7, rg = tid >> 3;  // 8 col-groups x5, 16 row-groups x8
    float acc[8][5];
    #pragma unroll
    for (int r = 0; r < 8; r++)
        #pragma unroll
        for (int c = 0; c < 5; c++) acc[r][c] = 0.f;

    for (int k0 = 0; k0 < F_IN; k0 += 16) {
        int r  = tid >> 2;
        int kc = (tid & 3) * 4;
        #pragma unroll
        for (int rr = 0; rr < 4; rr++) {
            int row = r + rr * 32;
            float4 v = make_float4(0.f, 0.f, 0.f, 0.f);
            if (i0 + row < N_NODES)
                v = *(const float4*)&g_h1[(size_t)(i0 + row) * F_IN + k0 + kc];
            As[kc + 0][row] = v.x; As[kc + 1][row] = v.y;
            As[kc + 2][row] = v.z; As[kc + 3][row] = v.w;
        }
        const float* bsrc = W2 + (size_t)k0 * C_OUT;
        #pragma unroll
        for (int i = 0; i < 5; i++) Bs[tid * 5 + i] = bsrc[tid * 5 + i];
        __syncthreads();
        #pragma unroll
        for (int kk = 0; kk < 16; kk++) {
            float a[8], b[5];
            *(float4*)&a[0] = *(float4*)&As[kk][rg * 8];
            *(float4*)&a[4] = *(float4*)&As[kk][rg * 8 + 4];
            #pragma unroll
            for (int i = 0; i < 5; i++) b[i] = Bs[kk * 40 + cg * 5 + i];
            #pragma unroll
            for (int r2 = 0; r2 < 8; r2++)
                #pragma unroll
                for (int c2 = 0; c2 < 5; c2++)
                    acc[r2][c2] += a[r2] * b[c2];
        }
        __syncthreads();
    }
    #pragma unroll
    for (int r = 0; r < 8; r++) {
        int row = i0 + rg * 8 + r;
        if (row < N_NODES) {
            #pragma unroll
            for (int c = 0; c < 5; c++)
                g_Wh2[(size_t)row * C_OUT + cg * 5 + c] = acc[r][c];
        }
    }
}

// ---------------- kernel 6: layer-2 scores ----------------
__global__ void scores2_kernel(const float* __restrict__ a_src2,
                               const float* __restrict__ a_tgt2) {
    int gw = (blockIdx.x * blockDim.x + threadIdx.x) >> 5;
    int lane = threadIdx.x & 31;
    if (gw >= N_NODES) return;
    float w1 = g_Wh2[(size_t)gw * C_OUT + lane];
    float as1 = a_src2[lane], at1 = a_tgt2[lane];
    float w2 = 0.f, as2 = 0.f, at2 = 0.f;
    if (lane + 32 < C_OUT) {
        w2 = g_Wh2[(size_t)gw * C_OUT + lane + 32];
        as2 = a_src2[lane + 32]; at2 = a_tgt2[lane + 32];
    }
    float ss = w1 * as1 + w2 * as2;
    float st = w1 * at1 + w2 * at2;
    #pragma unroll
    for (int o = 16; o > 0; o >>= 1) {
        ss += __shfl_xor_sync(0xFFFFFFFFu, ss, o);
        st += __shfl_xor_sync(0xFFFFFFFFu, st, o);
    }
    if (lane == 0) {
        g_S2src[gw] = ss; g_E2i[gw] = expf(ss); g_F2i[gw] = expf(ALPHA * ss);
        g_S2tgt[gw] = st; g_E2j[gw] = expf(st); g_F2j[gw] = expf(ALPHA * st);
    }
}

// ---------------- kernel 7: fused masked-softmax AV, layer 2 ----------------
// Same structure as av1; dims padded 40 -> 64 (zero-filled), store only d < 40.
__global__ void __launch_bounds__(128) av2_kernel(float* __restrict__ out) {
    __shared__ float w_s [TJ * TI];
    __shared__ float wh_s[TJ * 64];
    __shared__ float st_s[TJ], ej_s[TJ], fj_s[TJ];
    __shared__ float z_s[TI];

    int i0 = blockIdx.x * TI;
    int tid = threadIdx.x;
    int dg = tid & 7, rg = tid >> 3;

    int myrow = i0 + tid;
    bool rvalid = myrow < N_NODES;
    float Ei = 0.f, Fi = 0.f, ssrc = 0.f;
    if (rvalid) { Ei = g_E2i[myrow]; Fi = g_F2i[myrow]; ssrc = g_S2src[myrow]; }
    const unsigned* adjrow = &g_adjb[(size_t)(rvalid ? myrow : 0) * NW];

    float acc[8][8];
    #pragma unroll
    for (int r = 0; r < 8; r++)
        #pragma unroll
        for (int d = 0; d < 8; d++) acc[r][d] = 0.f;
    float zacc = 0.f;

    for (int j0 = 0; j0 < N_NODES; j0 += TJ) {
        #pragma unroll
        for (int r = 0; r < 4; r++) {
            int lin  = r * 512 + tid * 4;
            int jrow = lin >> 6;
            int c    = lin & 63;
            float4 v = make_float4(0.f, 0.f, 0.f, 0.f);
            if (j0 + jrow < N_NODES && c < C_OUT)
                v = *(const float4*)&g_Wh2[(size_t)(j0 + jrow) * C_OUT + c];
            *(float4*)&wh_s[lin] = v;
        }
        if (tid < TJ) {
            int j = j0 + tid;
            bool jv = j < N_NODES;
            st_s[tid] = jv ? g_S2tgt[j] : 0.f;
            ej_s[tid] = jv ? g_E2j[j] : 0.f;
            fj_s[tid] = jv ? g_F2j[j] : 0.f;
        }
        __syncthreads();
        {
            unsigned bits = rvalid ? adjrow[j0 >> 5] : 0u;
            #pragma unroll 8
            for (int k = 0; k < TJ; k++) {
                float m = (float)((bits >> k) & 1u);
                bool cond = (ssrc + st_s[k]) > 0.f;
                float w = m * (cond ? Ei * ej_s[k] : Fi * fj_s[k]);
                w_s[k * TI + tid] = w;
                zacc += w;
            }
        }
        __syncthreads();
        #pragma unroll 4
        for (int jj = 0; jj < TJ; jj++) {
            float a[8], b[8];
            *(float4*)&a[0] = *(float4*)&w_s[jj * TI + rg * 8];
            *(float4*)&a[4] = *(float4*)&w_s[jj * TI + rg * 8 + 4];
            *(float4*)&b[0] = *(float4*)&wh_s[jj * 64 + dg * 8];
            *(float4*)&b[4] = *(float4*)&wh_s[jj * 64 + dg * 8 + 4];
            #pragma unroll
            for (int r = 0; r < 8; r++)
                #pragma unroll
                for (int d = 0; d < 8; d++)
                    acc[r][d] += a[r] * b[d];
        }
        __syncthreads();
    }

    z_s[tid] = zacc;
    __syncthreads();

    if (dg < 5) {
        #pragma unroll
        for (int r = 0; r < 8; r++) {
            int iloc = rg * 8 + r;
            int row = i0 + iloc;
            if (row < N_NODES) {
                float invZ = 1.0f / z_s[iloc];
                float o[8];
                #pragma unroll
                for (int d = 0; d < 8; d++) o[d] = acc[r][d] * invZ;
                float* dst = &out[(size_t)row * C_OUT + dg * 8];
                *(float4*)&dst[0] = *(float4*)&o[0];
                *(float4*)&dst[4] = *(float4*)&o[4];
            }
        }
    }
}

// ---------------- launch ----------------
extern "C" void kernel_launch(void* const* d_in, const int* in_sizes, int n_in,
                              void* d_out, int out_size) {
    const float* x      = (const float*)d_in[0];
    const int*   adj    = (const int*)  d_in[1];
    const float* W1     = (const float*)d_in[2];
    const float* a_src1 = (const float*)d_in[3];
    const float* a_tgt1 = (const float*)d_in[4];
    const float* W2     = (const float*)d_in[5];
    const float* a_src2 = (const float*)d_in[6];
    const float* a_tgt2 = (const float*)d_in[7];
    float* out = (float*)d_out;

    // adj pack + output copy: 6000*188 warps exactly -> 141000 blocks of 256
    pack_adj_kernel<<<(N_NODES * NW * 32) / 256, 256>>>(adj, out, (long)out_size);

    gemm1_kernel<<<dim3((N_NODES + 63) / 64, H1), 128>>>(x, W1);
    scores1_kernel<<<(H1 * N_NODES * 32 + 255) / 256, 256>>>(a_src1, a_tgt1);
    av1_kernel<<<dim3((N_NODES + TI - 1) / TI, H1), 128>>>();

    gemm2_kernel<<<(N_NODES + 127) / 128, 128>>>(W2);
    scores2_kernel<<<(N_NODES * 32 + 255) / 256, 256>>>(a_src2, a_tgt2);
    av2_kernel<<<(N_NODES + TI - 1) / TI, 128>>>(out);
}

// round 4
// speedup vs baseline: 3.4191x; 3.4191x over previous
#include <cuda_runtime.h>
#include <cuda_fp16.h>
#include <math.h>
#include <stdint.h>

// ---------------- problem constants ----------------
#define N_NODES 6000
#define JP      6016           // N padded to multiple of 64 (j/K tiles)
#define F_IN    512
#define HID     64
#define H1      8
#define C_OUT   40
#define NW      188            // ceil(6000/32) words per adjacency row
#define ALPHA   0.2f
#define OUT_ADJ_OFF (N_NODES * C_OUT)

// ---------------- device scratch (static, allocation-free) ----------------
__device__ float    g_Wh  [H1 * N_NODES * HID];   // layer1 Wh fp32 (for scores)
__device__ __half   g_WhT [H1 * HID * (size_t)JP];// layer1 Wh^T fp16 [h][d][j], pad=0
__device__ unsigned g_adjb[N_NODES * NW];         // packed adjacency bits
__device__ float    g_h1  [N_NODES * (H1 * HID)]; // layer1 output (concat, post-ELU)
__device__ float    g_Wh2 [N_NODES * C_OUT];      // layer2 Wh fp32
__device__ __half   g_WhT2[HID * (size_t)JP];     // layer2 Wh^T fp16 [d pad64][j], pad=0

__device__ float g_Ssrc[H1 * N_NODES], g_Ei[H1 * N_NODES], g_Fi[H1 * N_NODES];
__device__ float g_Stgt[H1 * N_NODES], g_Ej[H1 * N_NODES], g_Fj[H1 * N_NODES];
__device__ float g_S2src[N_NODES], g_E2i[N_NODES], g_F2i[N_NODES];
__device__ float g_S2tgt[N_NODES], g_E2j[N_NODES], g_F2j[N_NODES];

// ---------------- warp-mma helpers (baseline PTX, sm_80+: OK on sm_100) ----------------
__device__ __forceinline__ uint32_t smem_u32(const void* p) {
    uint32_t a;
    asm("{ .reg .u64 t; cvta.to.shared.u64 t, %1; cvt.u32.u64 %0, t; }" : "=r"(a) : "l"(p));
    return a;
}
__device__ __forceinline__ void mma_16816(float c[4], const uint32_t a[4], const uint32_t b[2]) {
    asm volatile(
        "mma.sync.aligned.m16n8k16.row.col.f32.f16.f16.f32 "
        "{%0,%1,%2,%3}, {%4,%5,%6,%7}, {%8,%9}, {%0,%1,%2,%3};"
        : "+f"(c[0]), "+f"(c[1]), "+f"(c[2]), "+f"(c[3])
        : "r"(a[0]), "r"(a[1]), "r"(a[2]), "r"(a[3]), "r"(b[0]), "r"(b[1]));
}
__device__ __forceinline__ void ldsm_x4(uint32_t& r0, uint32_t& r1, uint32_t& r2, uint32_t& r3,
                                        uint32_t addr) {
    asm volatile("ldmatrix.sync.aligned.m8n8.x4.shared.b16 {%0,%1,%2,%3}, [%4];"
                 : "=r"(r0), "=r"(r1), "=r"(r2), "=r"(r3) : "r"(addr));
}
__device__ __forceinline__ uint32_t pack_h2(float x, float y) {
    __half2 h = __floats2half2_rn(x, y);
    return *(uint32_t*)&h;
}

// ---------------- kernel 1: pack adjacency bits + copy adj to output ----------------
__global__ void pack_adj_kernel(const int* __restrict__ adj,
                                float* __restrict__ outf, long out_size) {
    int gtid = blockIdx.x * blockDim.x + threadIdx.x;
    int warp = gtid >> 5, lane = gtid & 31;
    int row = warp / NW, wj = warp % NW;
    int j = wj * 32 + lane;
    int v = 0;
    if (j < N_NODES) {
        long idx = (long)row * N_NODES + j;
        v = adj[idx];
        long oi = (long)OUT_ADJ_OFF + idx;
        if (oi < out_size) outf[oi] = (float)v;
    }
    unsigned bits = __ballot_sync(0xFFFFFFFFu, v != 0);
    if (lane == 0) g_adjb[row * NW + wj] = bits;
}

// ---------------- kernel 2: Wh = x @ W1[h]; also emit WhT fp16 ----------------
__global__ void __launch_bounds__(128) gemm1_kernel(const float* __restrict__ x,
                                                    const float* __restrict__ W1) {
    __shared__ float As[16][64];
    __shared__ float Bs[16 * 64];
    int h  = blockIdx.y;
    int i0 = blockIdx.x * 64;
    int tid = threadIdx.x;
    int tc = tid & 15, tr = tid >> 4;
    const float* Bsrc = W1 + (size_t)h * F_IN * HID;
    float acc[8][4];
    #pragma unroll
    for (int r = 0; r < 8; r++)
        #pragma unroll
        for (int c = 0; c < 4; c++) acc[r][c] = 0.f;

    for (int k0 = 0; k0 < F_IN; k0 += 16) {
        int r  = tid >> 2;
        int kc = (tid & 3) * 4;
        #pragma unroll
        for (int rr = 0; rr < 2; rr++) {
            int row = r + rr * 32;
            float4 v = make_float4(0.f, 0.f, 0.f, 0.f);
            if (i0 + row < N_NODES)
                v = *(const float4*)&x[(size_t)(i0 + row) * F_IN + k0 + kc];
            As[kc + 0][row] = v.x; As[kc + 1][row] = v.y;
            As[kc + 2][row] = v.z; As[kc + 3][row] = v.w;
        }
        const float4* bs = (const float4*)(Bsrc + (size_t)k0 * HID);
        float4* bd = (float4*)Bs;
        bd[tid]       = bs[tid];
        bd[tid + 128] = bs[tid + 128];
        __syncthreads();
        #pragma unroll
        for (int kk = 0; kk < 16; kk++) {
            float a[8], b[4];
            *(float4*)&a[0] = *(float4*)&As[kk][tr * 8];
            *(float4*)&a[4] = *(float4*)&As[kk][tr * 8 + 4];
            *(float4*)&b[0] = *(float4*)&Bs[kk * 64 + tc * 4];
            #pragma unroll
            for (int rr = 0; rr < 8; rr++)
                #pragma unroll
                for (int cc = 0; cc < 4; cc++)
                    acc[rr][cc] += a[rr] * b[cc];
        }
        __syncthreads();
    }
    bool gvalid = (i0 + tr * 8) < N_NODES;   // 6000 % 8 == 0
    #pragma unroll
    for (int rr = 0; rr < 8; rr++) {
        int row = i0 + tr * 8 + rr;
        if (row < N_NODES)
            *(float4*)&g_Wh[((size_t)h * N_NODES + row) * HID + tc * 4] = *(float4*)&acc[rr][0];
    }
    #pragma unroll
    for (int cc = 0; cc < 4; cc++) {
        int col = tc * 4 + cc;
        __half tmp[8];
        #pragma unroll
        for (int rr = 0; rr < 8; rr++) tmp[rr] = __float2half_rn(acc[rr][cc]);
        if (gvalid)
            *(uint4*)&g_WhT[((size_t)h * HID + col) * JP + i0 + tr * 8] = *(uint4*)tmp;
    }
}

// ---------------- kernel 3: per-node scores + exponentials (layer 1) ----------------
__global__ void scores1_kernel(const float* __restrict__ a_src,
                               const float* __restrict__ a_tgt) {
    int gw = (blockIdx.x * blockDim.x + threadIdx.x) >> 5;
    int lane = threadIdx.x & 31;
    if (gw >= H1 * N_NODES) return;
    int h = gw / N_NODES, n = gw % N_NODES;
    const float* wh = &g_Wh[((size_t)h * N_NODES + n) * HID];
    float w1 = wh[lane], w2 = wh[lane + 32];
    float ss = w1 * a_src[h * HID + lane] + w2 * a_src[h * HID + lane + 32];
    float st = w1 * a_tgt[h * HID + lane] + w2 * a_tgt[h * HID + lane + 32];
    #pragma unroll
    for (int o = 16; o > 0; o >>= 1) {
        ss += __shfl_xor_sync(0xFFFFFFFFu, ss, o);
        st += __shfl_xor_sync(0xFFFFFFFFu, st, o);
    }
    if (lane == 0) {
        g_Ssrc[gw] = ss; g_Ei[gw] = expf(ss); g_Fi[gw] = expf(ALPHA * ss);
        g_Stgt[gw] = st; g_Ej[gw] = expf(st); g_Fj[gw] = expf(ALPHA * st);
    }
}

// ---------------- fused masked-softmax AV on mma.sync tensor cores ----------------
// Block: 256 threads = 8 warps, each warp owns 16 i-rows -> 128 rows/block.
// Per j-tile (64): stage WhT B-tile in smem (stride 72, ldmatrix-friendly);
// A (weight) fragments computed DIRECTLY in registers in mma layout; Z in fp32.
// NG = n-groups stored/multiplied (8 for layer1 D=64, 5 for layer2 D=40).
template<int NG, int NGL, bool L2K>
__global__ void __launch_bounds__(256) av_mma_kernel(float* __restrict__ out) {
    __shared__ __half whT_s[64 * 72];     // [n(dim)][k(j)] padded
    __shared__ float  s_st[64];
    __shared__ float2 s_ef[64];           // (Ej, Fj)

    int tid = threadIdx.x;
    int lane = tid & 31, warp = tid >> 5;
    int h  = blockIdx.y;
    int i0 = blockIdx.x * 128;

    const float *Ssrc, *Eiv, *Fiv, *Stgt, *Ejv, *Fjv;
    const __half* whT;
    if (L2K) {
        Ssrc = g_S2src; Eiv = g_E2i; Fiv = g_F2i;
        Stgt = g_S2tgt; Ejv = g_E2j; Fjv = g_F2j;
        whT = g_WhT2;
    } else {
        int hb = h * N_NODES;
        Ssrc = g_Ssrc + hb; Eiv = g_Ei + hb; Fiv = g_Fi + hb;
        Stgt = g_Stgt + hb; Ejv = g_Ej + hb; Fjv = g_Fj + hb;
        whT = g_WhT + (size_t)h * HID * JP;
    }

    // per-thread rows: rr=0 -> r0, rr=1 -> r0+8
    int r0 = i0 + warp * 16 + (lane >> 2);
    int rowc[2] = { min(r0, N_NODES - 1), min(r0 + 8, N_NODES - 1) };
    float Eir[2], Fir[2], ssr[2], z[2] = {0.f, 0.f};
    #pragma unroll
    for (int rr = 0; rr < 2; rr++) {
        Eir[rr] = Eiv[rowc[rr]];
        Fir[rr] = Fiv[rowc[rr]];
        ssr[rr] = Ssrc[rowc[rr]];
    }

    int cb = (lane & 3) * 2;

    // B ldmatrix per-thread base address
    int nb = (lane & 7) | (((lane >> 4) & 1) << 3);
    int kb = ((lane >> 3) & 1) * 8;
    uint32_t b_base = smem_u32(whT_s) + (uint32_t)(nb * 72 + kb) * 2;

    float acc[NG][4];
    #pragma unroll
    for (int g = 0; g < NG; g++)
        #pragma unroll
        for (int c = 0; c < 4; c++) acc[g][c] = 0.f;

    // B staging: thread -> row n = tid>>2, quarter q = tid&3 (16 halves)
    int snr = tid >> 2, sq = tid & 3;
    const __half* bsrc_row = whT + (size_t)snr * JP + sq * 16;

    for (int t = 0; t < JP / 64; t++) {
        int j0 = t * 64;
        // ---- stage B tile + per-j scalars ----
        {
            const uint4* src = (const uint4*)(bsrc_row + j0);
            uint4* dst = (uint4*)&whT_s[snr * 72 + sq * 16];
            dst[0] = src[0];
            dst[1] = src[1];
        }
        if (tid < 64) {
            int j = j0 + tid;
            bool jv = j < N_NODES;
            s_st[tid] = jv ? Stgt[j] : 0.f;
            s_ef[tid] = jv ? make_float2(Ejv[j], Fjv[j]) : make_float2(0.f, 0.f);
        }
        // adjacency words for my 2 rows (this tile covers bits [j0, j0+64))
        uint2 aw[2];
        aw[0] = *(const uint2*)&g_adjb[(size_t)rowc[0] * NW + 2 * t];
        aw[1] = *(const uint2*)&g_adjb[(size_t)rowc[1] * NW + 2 * t];
        __syncthreads();

        #pragma unroll
        for (int ks = 0; ks < 4; ks++) {
            int jb = ks * 16 + cb;
            float  t0 = s_st[jb],     t1 = s_st[jb + 1];
            float  t8 = s_st[jb + 8], t9 = s_st[jb + 9];
            float2 e0 = s_ef[jb],     e1 = s_ef[jb + 1];
            float2 e8 = s_ef[jb + 8], e9 = s_ef[jb + 9];

            uint32_t a[4];
            #pragma unroll
            for (int rr = 0; rr < 2; rr++) {
                unsigned word = (ks < 2) ? aw[rr].x : aw[rr].y;
                int sh = ((ks & 1) << 4) + cb;
                float E = Eir[rr], F = Fir[rr], S = ssr[rr];
                float w0 = ((word >> sh) & 1u)       ? ((S + t0 > 0.f) ? E * e0.x : F * e0.y) : 0.f;
                float w1 = ((word >> (sh + 1)) & 1u) ? ((S + t1 > 0.f) ? E * e1.x : F * e1.y) : 0.f;
                float w8 = ((word >> (sh + 8)) & 1u) ? ((S + t8 > 0.f) ? E * e8.x : F * e8.y) : 0.f;
                float w9 = ((word >> (sh + 9)) & 1u) ? ((S + t9 > 0.f) ? E * e9.x : F * e9.y) : 0.f;
                z[rr] += (w0 + w1) + (w8 + w9);
                a[rr]     = pack_h2(w0, w1);
                a[rr + 2] = pack_h2(w8, w9);
            }

            uint32_t b[NGL][2];
            #pragma unroll
            for (int p = 0; p < NGL / 2; p++)
                ldsm_x4(b[2 * p][0], b[2 * p][1], b[2 * p + 1][0], b[2 * p + 1][1],
                        b_base + (uint32_t)(p * 16 * 72 + ks * 16) * 2);

            #pragma unroll
            for (int g = 0; g < NG; g++)
                mma_16816(acc[g], a, b[g]);
        }
        __syncthreads();
    }

    // ---- Z reduce across the 4 lanes sharing each row ----
    #pragma unroll
    for (int rr = 0; rr < 2; rr++) {
        z[rr] += __shfl_xor_sync(0xFFFFFFFFu, z[rr], 1);
        z[rr] += __shfl_xor_sync(0xFFFFFFFFu, z[rr], 2);
    }

    // ---- epilogue: normalize, (ELU), store ----
    #pragma unroll
    for (int rr = 0; rr < 2; rr++) {
        int row = r0 + rr * 8;
        if (row >= N_NODES) continue;
        float invZ = 1.0f / z[rr];
        #pragma unroll
        for (int g = 0; g < NG; g++) {
            float v0 = acc[g][rr * 2]     * invZ;
            float v1 = acc[g][rr * 2 + 1] * invZ;
            if (L2K) {
                float2* dst = (float2*)&out[(size_t)row * C_OUT + g * 8 + cb];
                *dst = make_float2(v0, v1);
            } else {
                v0 = v0 > 0.f ? v0 : expm1f(v0);
                v1 = v1 > 0.f ? v1 : expm1f(v1);
                float2* dst = (float2*)&g_h1[(size_t)row * (H1 * HID) + h * HID + g * 8 + cb];
                *dst = make_float2(v0, v1);
            }
        }
    }
}

// ---------------- kernel 5: Wh2 = h1 @ W2; also emit WhT2 fp16 ----------------
__global__ void __launch_bounds__(128) gemm2_kernel(const float* __restrict__ W2) {
    __shared__ float As[16][128];
    __shared__ float Bs[16 * 40];
    int i0 = blockIdx.x * 128;
    int tid = threadIdx.x;
    int cg = tid & 7, rg = tid >> 3;
    float acc[8][5];
    #pragma unroll
    for (int r = 0; r < 8; r++)
        #pragma unroll
        for (int c = 0; c < 5; c++) acc[r][c] = 0.f;

    for (int k0 = 0; k0 < F_IN; k0 += 16) {
        int r  = tid >> 2;
        int kc = (tid & 3) * 4;
        #pragma unroll
        for (int rr = 0; rr < 4; rr++) {
            int row = r + rr * 32;
            float4 v = make_float4(0.f, 0.f, 0.f, 0.f);
            if (i0 + row < N_NODES)
                v = *(const float4*)&g_h1[(size_t)(i0 + row) * F_IN + k0 + kc];
            As[kc + 0][row] = v.x; As[kc + 1][row] = v.y;
            As[kc + 2][row] = v.z; As[kc + 3][row] = v.w;
        }
        const float* bsrc = W2 + (size_t)k0 * C_OUT;
        #pragma unroll
        for (int i = 0; i < 5; i++) Bs[tid * 5 + i] = bsrc[tid * 5 + i];
        __syncthreads();
        #pragma unroll
        for (int kk = 0; kk < 16; kk++) {
            float a[8], b[5];
            *(float4*)&a[0] = *(float4*)&As[kk][rg * 8];
            *(float4*)&a[4] = *(float4*)&As[kk][rg * 8 + 4];
            #pragma unroll
            for (int i = 0; i < 5; i++) b[i] = Bs[kk * 40 + cg * 5 + i];
            #pragma unroll
            for (int r2 = 0; r2 < 8; r2++)
                #pragma unroll
                for (int c2 = 0; c2 < 5; c2++)
                    acc[r2][c2] += a[r2] * b[c2];
        }
        __syncthreads();
    }
    bool gvalid = (i0 + rg * 8) < N_NODES;
    #pragma unroll
    for (int r = 0; r < 8; r++) {
        int row = i0 + rg * 8 + r;
        if (row < N_NODES) {
            #pragma unroll
            for (int c = 0; c < 5; c++)
                g_Wh2[(size_t)row * C_OUT + cg * 5 + c] = acc[r][c];
        }
    }
    #pragma unroll
    for (int c = 0; c < 5; c++) {
        int col = cg * 5 + c;
        __half tmp[8];
        #pragma unroll
        for (int r2 = 0; r2 < 8; r2++) tmp[r2] = __float2half_rn(acc[r2][c]);
        if (gvalid)
            *(uint4*)&g_WhT2[(size_t)col * JP + i0 + rg * 8] = *(uint4*)tmp;
    }
}

// ---------------- kernel 6: layer-2 scores ----------------
__global__ void scores2_kernel(const float* __restrict__ a_src2,
                               const float* __restrict__ a_tgt2) {
    int gw = (blockIdx.x * blockDim.x + threadIdx.x) >> 5;
    int lane = threadIdx.x & 31;
    if (gw >= N_NODES) return;
    float w1 = g_Wh2[(size_t)gw * C_OUT + lane];
    float as1 = a_src2[lane], at1 = a_tgt2[lane];
    float w2 = 0.f, as2 = 0.f, at2 = 0.f;
    if (lane + 32 < C_OUT) {
        w2 = g_Wh2[(size_t)gw * C_OUT + lane + 32];
        as2 = a_src2[lane + 32]; at2 = a_tgt2[lane + 32];
    }
    float ss = w1 * as1 + w2 * as2;
    float st = w1 * at1 + w2 * at2;
    #pragma unroll
    for (int o = 16; o > 0; o >>= 1) {
        ss += __shfl_xor_sync(0xFFFFFFFFu, ss, o);
        st += __shfl_xor_sync(0xFFFFFFFFu, st, o);
    }
    if (lane == 0) {
        g_S2src[gw] = ss; g_E2i[gw] = expf(ss); g_F2i[gw] = expf(ALPHA * ss);
        g_S2tgt[gw] = st; g_E2j[gw] = expf(st); g_F2j[gw] = expf(ALPHA * st);
    }
}

// ---------------- launch ----------------
extern "C" void kernel_launch(void* const* d_in, const int* in_sizes, int n_in,
                              void* d_out, int out_size) {
    const float* x      = (const float*)d_in[0];
    const int*   adj    = (const int*)  d_in[1];
    const float* W1     = (const float*)d_in[2];
    const float* a_src1 = (const float*)d_in[3];
    const float* a_tgt1 = (const float*)d_in[4];
    const float* W2     = (const float*)d_in[5];
    const float* a_src2 = (const float*)d_in[6];
    const float* a_tgt2 = (const float*)d_in[7];
    float* out = (float*)d_out;

    pack_adj_kernel<<<(N_NODES * NW * 32) / 256, 256>>>(adj, out, (long)out_size);

    gemm1_kernel<<<dim3((N_NODES + 63) / 64, H1), 128>>>(x, W1);
    scores1_kernel<<<(H1 * N_NODES * 32 + 255) / 256, 256>>>(a_src1, a_tgt1);
    av_mma_kernel<8, 8, false><<<dim3((N_NODES + 127) / 128, H1), 256>>>(nullptr);

    gemm2_kernel<<<(N_NODES + 127) / 128, 128>>>(W2);
    scores2_kernel<<<(N_NODES * 32 + 255) / 256, 256>>>(a_src2, a_tgt2);
    av_mma_kernel<5, 6, true><<<dim3((N_NODES + 127) / 128, 1), 256>>>(out);
}

// round 5
// speedup vs baseline: 4.3044x; 1.2589x over previous
#include <cuda_runtime.h>
#include <cuda_fp16.h>
#include <math.h>
#include <stdint.h>

// ---------------- problem constants ----------------
#define N_NODES 6000
#define JP      6016           // N padded to multiple of 64 (j/K tiles)
#define F_IN    512
#define HID     64
#define H1      8
#define C_OUT   40
#define NW      188            // ceil(6000/32) words per adjacency row
#define ALPHA   0.2f
#define OUT_ADJ_OFF (N_NODES * C_OUT)
#define NT_FULL 94             // JP/64

// ---------------- device scratch (static, allocation-free) ----------------
__device__ float    g_Wh  [H1 * N_NODES * HID];   // layer1 Wh fp32 (for scores)
__device__ __half   g_WhT [H1 * HID * (size_t)JP];// layer1 Wh^T fp16 [h][d][j], pad=0
__device__ unsigned g_adjb[N_NODES * NW];         // packed adjacency bits
__device__ float    g_h1  [N_NODES * (H1 * HID)]; // layer1 output (concat, post-ELU)
__device__ float    g_Wh2 [N_NODES * C_OUT];      // layer2 Wh fp32
__device__ __half   g_WhT2[HID * (size_t)JP];     // layer2 Wh^T fp16 [d pad64][j], pad=0
__device__ float    g_part[2 * 6016 * 48];        // layer2 partials (D cols 0..39, Z at 40)

__device__ float  g_Ssrc[H1 * N_NODES], g_Ei[H1 * N_NODES], g_Fi[H1 * N_NODES];
__device__ float  g_S2src[N_NODES], g_E2i[N_NODES], g_F2i[N_NODES];
// half-packed target-side per-node tables (zero in padded region)
__device__ __half g_st1h[H1 * JP], g_e1h[H1 * JP], g_f1h[H1 * JP];
__device__ __half g_st2h[JP],      g_e2h[JP],      g_f2h[JP];

// ---------------- helpers ----------------
__device__ __forceinline__ uint32_t smem_u32(const void* p) {
    uint32_t a;
    asm("{ .reg .u64 t; cvta.to.shared.u64 t, %1; cvt.u32.u64 %0, t; }" : "=r"(a) : "l"(p));
    return a;
}
__device__ __forceinline__ void mma_16816(float c[4], const uint32_t a[4], const uint32_t b[2]) {
    asm volatile(
        "mma.sync.aligned.m16n8k16.row.col.f32.f16.f16.f32 "
        "{%0,%1,%2,%3}, {%4,%5,%6,%7}, {%8,%9}, {%0,%1,%2,%3};"
        : "+f"(c[0]), "+f"(c[1]), "+f"(c[2]), "+f"(c[3])
        : "r"(a[0]), "r"(a[1]), "r"(a[2]), "r"(a[3]), "r"(b[0]), "r"(b[1]));
}
__device__ __forceinline__ void ldsm_x4(uint32_t& r0, uint32_t& r1, uint32_t& r2, uint32_t& r3,
                                        uint32_t addr) {
    asm volatile("ldmatrix.sync.aligned.m8n8.x4.shared.b16 {%0,%1,%2,%3}, [%4];"
                 : "=r"(r0), "=r"(r1), "=r"(r2), "=r"(r3) : "r"(addr));
}
#define CP_ASYNC16(dst, src) \
    asm volatile("cp.async.cg.shared.global [%0], [%1], 16;" :: "r"(dst), "l"(src))
#define CP_COMMIT() asm volatile("cp.async.commit_group;" ::: "memory")
#define CP_WAIT1()  asm volatile("cp.async.wait_group 1;" ::: "memory")
#define CP_WAIT0()  asm volatile("cp.async.wait_group 0;" ::: "memory")

// ---------------- kernel 1: pack adjacency bits + copy adj to output ----------------
__global__ void pack_adj_kernel(const int* __restrict__ adj,
                                float* __restrict__ outf, long out_size) {
    int gtid = blockIdx.x * blockDim.x + threadIdx.x;
    int warp = gtid >> 5, lane = gtid & 31;
    int row = warp / NW, wj = warp % NW;
    int j = wj * 32 + lane;
    int v = 0;
    if (j < N_NODES) {
        long idx = (long)row * N_NODES + j;
        v = adj[idx];
        long oi = (long)OUT_ADJ_OFF + idx;
        if (oi < out_size) outf[oi] = (float)v;
    }
    unsigned bits = __ballot_sync(0xFFFFFFFFu, v != 0);
    if (lane == 0) g_adjb[row * NW + wj] = bits;
}

// ---------------- kernel 2: Wh = x @ W1[h]; also emit WhT fp16 ----------------
__global__ void __launch_bounds__(128) gemm1_kernel(const float* __restrict__ x,
                                                    const float* __restrict__ W1) {
    __shared__ float As[16][64];
    __shared__ float Bs[16 * 64];
    int h  = blockIdx.y;
    int i0 = blockIdx.x * 64;
    int tid = threadIdx.x;
    int tc = tid & 15, tr = tid >> 4;
    const float* Bsrc = W1 + (size_t)h * F_IN * HID;
    float acc[8][4];
    #pragma unroll
    for (int r = 0; r < 8; r++)
        #pragma unroll
        for (int c = 0; c < 4; c++) acc[r][c] = 0.f;

    for (int k0 = 0; k0 < F_IN; k0 += 16) {
        int r  = tid >> 2;
        int kc = (tid & 3) * 4;
        #pragma unroll
        for (int rr = 0; rr < 2; rr++) {
            int row = r + rr * 32;
            float4 v = make_float4(0.f, 0.f, 0.f, 0.f);
            if (i0 + row < N_NODES)
                v = *(const float4*)&x[(size_t)(i0 + row) * F_IN + k0 + kc];
            As[kc + 0][row] = v.x; As[kc + 1][row] = v.y;
            As[kc + 2][row] = v.z; As[kc + 3][row] = v.w;
        }
        const float4* bs = (const float4*)(Bsrc + (size_t)k0 * HID);
        float4* bd = (float4*)Bs;
        bd[tid]       = bs[tid];
        bd[tid + 128] = bs[tid + 128];
        __syncthreads();
        #pragma unroll
        for (int kk = 0; kk < 16; kk++) {
            float a[8], b[4];
            *(float4*)&a[0] = *(float4*)&As[kk][tr * 8];
            *(float4*)&a[4] = *(float4*)&As[kk][tr * 8 + 4];
            *(float4*)&b[0] = *(float4*)&Bs[kk * 64 + tc * 4];
            #pragma unroll
            for (int rr = 0; rr < 8; rr++)
                #pragma unroll
                for (int cc = 0; cc < 4; cc++)
                    acc[rr][cc] += a[rr] * b[cc];
        }
        __syncthreads();
    }
    bool gvalid = (i0 + tr * 8) < N_NODES;
    #pragma unroll
    for (int rr = 0; rr < 8; rr++) {
        int row = i0 + tr * 8 + rr;
        if (row < N_NODES)
            *(float4*)&g_Wh[((size_t)h * N_NODES + row) * HID + tc * 4] = *(float4*)&acc[rr][0];
    }
    #pragma unroll
    for (int cc = 0; cc < 4; cc++) {
        int col = tc * 4 + cc;
        __half tmp[8];
        #pragma unroll
        for (int rr = 0; rr < 8; rr++) tmp[rr] = __float2half_rn(acc[rr][cc]);
        if (gvalid)
            *(uint4*)&g_WhT[((size_t)h * HID + col) * JP + i0 + tr * 8] = *(uint4*)tmp;
    }
}

// ---------------- kernel 3: per-node scores + exponentials (layer 1) ----------------
__global__ void scores1_kernel(const float* __restrict__ a_src,
                               const float* __restrict__ a_tgt) {
    int gw = (blockIdx.x * blockDim.x + threadIdx.x) >> 5;
    int lane = threadIdx.x & 31;
    if (gw >= H1 * N_NODES) return;
    int h = gw / N_NODES, n = gw % N_NODES;
    const float* wh = &g_Wh[((size_t)h * N_NODES + n) * HID];
    float w1 = wh[lane], w2 = wh[lane + 32];
    float ss = w1 * a_src[h * HID + lane] + w2 * a_src[h * HID + lane + 32];
    float st = w1 * a_tgt[h * HID + lane] + w2 * a_tgt[h * HID + lane + 32];
    #pragma unroll
    for (int o = 16; o > 0; o >>= 1) {
        ss += __shfl_xor_sync(0xFFFFFFFFu, ss, o);
        st += __shfl_xor_sync(0xFFFFFFFFu, st, o);
    }
    if (lane == 0) {
        g_Ssrc[gw] = ss; g_Ei[gw] = expf(ss); g_Fi[gw] = expf(ALPHA * ss);
        size_t hi = (size_t)h * JP + n;
        g_st1h[hi] = __float2half_rn(st);
        g_e1h [hi] = __float2half_rn(expf(st));
        g_f1h [hi] = __float2half_rn(expf(ALPHA * st));
    }
}

// ---------------- fused masked-softmax AV on mma.sync ----------------
// 128 threads = 4 warps, 64 i-rows/block. Z computed via constant ones-column MMA.
// cp.async double-buffered B tile + per-j half scalars; half2 weight build.
template<int NG, int NGL, bool L2K>
__global__ void __launch_bounds__(128, 5) av_mma_kernel(float* __restrict__ dummy) {
    __shared__ __align__(16) __half Bbuf[2][64 * 72];
    __shared__ __align__(16) __half stb[2][64];
    __shared__ __align__(16) __half eb [2][64];
    __shared__ __align__(16) __half fb [2][64];

    int tid = threadIdx.x;
    int lane = tid & 31, warp = tid >> 5;
    int i0 = blockIdx.x * 64;

    const float *Ssrc, *Eiv, *Fiv;
    const __half *sth, *ehp, *fhp, *whT;
    int tbeg, tend;
    if (L2K) {
        Ssrc = g_S2src; Eiv = g_E2i; Fiv = g_F2i;
        sth = g_st2h; ehp = g_e2h; fhp = g_f2h;
        whT = g_WhT2;
        tbeg = blockIdx.y * (NT_FULL / 2); tend = tbeg + NT_FULL / 2;
    } else {
        int h = blockIdx.y;
        int hb = h * N_NODES;
        Ssrc = g_Ssrc + hb; Eiv = g_Ei + hb; Fiv = g_Fi + hb;
        size_t hj = (size_t)h * JP;
        sth = g_st1h + hj; ehp = g_e1h + hj; fhp = g_f1h + hj;
        whT = g_WhT + (size_t)h * HID * JP;
        tbeg = 0; tend = NT_FULL;
    }

    // rows: rr=0 -> r0, rr=1 -> r0+8
    int r0 = i0 + warp * 16 + (lane >> 2);
    int rowc[2] = { min(r0, N_NODES - 1), min(r0 + 8, N_NODES - 1) };
    __half2 S2[2], E2[2], F2[2];
    #pragma unroll
    for (int rr = 0; rr < 2; rr++) {
        S2[rr] = __half2half2(__float2half_rn(Ssrc[rowc[rr]]));
        E2[rr] = __half2half2(__float2half_rn(Eiv[rowc[rr]]));
        F2[rr] = __half2half2(__float2half_rn(Fiv[rowc[rr]]));
    }
    int cb = (lane & 3) * 2;

    // ldsm base (per buffer)
    int nb = (lane & 7) | (((lane >> 4) & 1) << 3);
    int kb = ((lane >> 3) & 1) * 8;
    uint32_t bB[2] = { smem_u32(Bbuf[0]), smem_u32(Bbuf[1]) };
    uint32_t bST[2] = { smem_u32(stb[0]), smem_u32(stb[1]) };
    uint32_t bE[2]  = { smem_u32(eb[0]),  smem_u32(eb[1])  };
    uint32_t bF[2]  = { smem_u32(fb[0]),  smem_u32(fb[1])  };
    uint32_t lds_off = (uint32_t)(nb * 72 + kb) * 2;

    float acc[NG][4];
    float accz[4];
    #pragma unroll
    for (int g = 0; g < NG; g++)
        #pragma unroll
        for (int c = 0; c < 4; c++) acc[g][c] = 0.f;
    #pragma unroll
    for (int c = 0; c < 4; c++) accz[c] = 0.f;

    const uint32_t ONES2 = 0x3C003C00u;
    const uint32_t bz[2] = { ONES2, ONES2 };
    const __half2 zero2 = __float2half2_rn(0.f);

    int NT = tend - tbeg;

    // ---- stage helper (inline) ----
    auto stage = [&](int t, int b) {
        int j0 = (tbeg + t) * 64;
        #pragma unroll
        for (int i2 = 0; i2 < 4; i2++) {
            int c = tid + 128 * i2;
            int n = c >> 3, o = c & 7;
            CP_ASYNC16(bB[b] + (uint32_t)(n * 144 + o * 16),
                       whT + (size_t)n * JP + j0 + o * 8);
        }
        if (tid >= 96 && tid < 120) {
            int a2 = tid - 96;
            int arr = a2 >> 3, ch = a2 & 7;
            const __half* src = (arr == 0 ? sth : arr == 1 ? ehp : fhp) + j0 + ch * 8;
            uint32_t dst = (arr == 0 ? bST[b] : arr == 1 ? bE[b] : bF[b]) + (uint32_t)ch * 16;
            CP_ASYNC16(dst, src);
        }
    };

    stage(0, 0);
    CP_COMMIT();

    for (int t = 0; t < NT; t++) {
        int b = t & 1;
        if (t + 1 < NT) { stage(t + 1, (t + 1) & 1); CP_COMMIT(); CP_WAIT1(); }
        else            { CP_COMMIT(); CP_WAIT0(); }
        __syncthreads();

        int tg = tbeg + t;
        uint2 aw[2];
        aw[0] = *(const uint2*)&g_adjb[(size_t)rowc[0] * NW + 2 * tg];
        aw[1] = *(const uint2*)&g_adjb[(size_t)rowc[1] * NW + 2 * tg];

        #pragma unroll
        for (int ks = 0; ks < 4; ks++) {
            int jb = ks * 16 + cb;
            __half2 st2a = *(__half2*)&stb[b][jb];
            __half2 st2b = *(__half2*)&stb[b][jb + 8];
            __half2 e2a  = *(__half2*)&eb[b][jb];
            __half2 e2b  = *(__half2*)&eb[b][jb + 8];
            __half2 f2a  = *(__half2*)&fb[b][jb];
            __half2 f2b  = *(__half2*)&fb[b][jb + 8];

            uint32_t a[4];
            #pragma unroll
            for (int rr = 0; rr < 2; rr++) {
                unsigned word = (ks < 2) ? aw[rr].x : aw[rr].y;
                unsigned ta = word >> (((ks & 1) << 4) + cb);
                unsigned tbits = ta >> 8;
                uint32_t ma = ((ta & 1u) ? 0x3C00u : 0u) | ((ta & 2u) ? 0x3C000000u : 0u);
                uint32_t mb = ((tbits & 1u) ? 0x3C00u : 0u) | ((tbits & 2u) ? 0x3C000000u : 0u);

                __half2 m2  = __hgt2(__hadd2(S2[rr], st2a), zero2);
                __half2 Ee  = __hmul2(E2[rr], e2a);
                __half2 Ff  = __hmul2(F2[rr], f2a);
                __half2 wa  = __hfma2(m2, __hsub2(Ee, Ff), Ff);
                wa = __hmul2(wa, *(__half2*)&ma);

                __half2 m2b = __hgt2(__hadd2(S2[rr], st2b), zero2);
                __half2 Eeb = __hmul2(E2[rr], e2b);
                __half2 Ffb = __hmul2(F2[rr], f2b);
                __half2 wbv = __hfma2(m2b, __hsub2(Eeb, Ffb), Ffb);
                wbv = __hmul2(wbv, *(__half2*)&mb);

                a[rr]     = *(uint32_t*)&wa;
                a[rr + 2] = *(uint32_t*)&wbv;
            }

            uint32_t bf[NGL][2];
            #pragma unroll
            for (int p = 0; p < NGL / 2; p++)
                ldsm_x4(bf[2 * p][0], bf[2 * p][1], bf[2 * p + 1][0], bf[2 * p + 1][1],
                        bB[b] + lds_off + (uint32_t)(p * 16 * 144 + ks * 32));

            #pragma unroll
            for (int g = 0; g < NG; g++)
                mma_16816(acc[g], a, bf[g]);
            mma_16816(accz, a, bz);
        }
        __syncthreads();
    }

    // ---- epilogue ----
    #pragma unroll
    for (int rr = 0; rr < 2; rr++) {
        int row = r0 + rr * 8;
        if (row >= N_NODES) continue;
        if (L2K) {
            size_t base = ((size_t)blockIdx.y * 6016 + row) * 48;
            #pragma unroll
            for (int g = 0; g < NG; g++)
                *(float2*)&g_part[base + g * 8 + cb] =
                    make_float2(acc[g][rr * 2], acc[g][rr * 2 + 1]);
            if (cb == 0) g_part[base + 40] = accz[rr * 2];
        } else {
            float invZ = 1.0f / accz[rr * 2];
            int h = blockIdx.y;
            #pragma unroll
            for (int g = 0; g < NG; g++) {
                float v0 = acc[g][rr * 2]     * invZ;
                float v1 = acc[g][rr * 2 + 1] * invZ;
                v0 = v0 > 0.f ? v0 : expm1f(v0);
                v1 = v1 > 0.f ? v1 : expm1f(v1);
                *(float2*)&g_h1[(size_t)row * (H1 * HID) + h * HID + g * 8 + cb] =
                    make_float2(v0, v1);
            }
        }
    }
}

// ---------------- layer-2 partial combine ----------------
__global__ void combine2_kernel(float* __restrict__ out) {
    int idx = blockIdx.x * blockDim.x + threadIdx.x;
    if (idx >= N_NODES * C_OUT) return;
    int row = idx / C_OUT, c = idx - row * C_OUT;
    size_t b0 = (size_t)row * 48, b1 = (size_t)(6016 + row) * 48;
    float z = g_part[b0 + 40] + g_part[b1 + 40];
    out[idx] = (g_part[b0 + c] + g_part[b1 + c]) / z;
}

// ---------------- kernel 5: Wh2 = h1 @ W2; also emit WhT2 fp16 ----------------
__global__ void __launch_bounds__(128) gemm2_kernel(const float* __restrict__ W2) {
    __shared__ float As[16][128];
    __shared__ float Bs[16 * 40];
    int i0 = blockIdx.x * 128;
    int tid = threadIdx.x;
    int cg = tid & 7, rg = tid >> 3;
    float acc[8][5];
    #pragma unroll
    for (int r = 0; r < 8; r++)
        #pragma unroll
        for (int c = 0; c < 5; c++) acc[r][c] = 0.f;

    for (int k0 = 0; k0 < F_IN; k0 += 16) {
        int r  = tid >> 2;
        int kc = (tid & 3) * 4;
        #pragma unroll
        for (int rr = 0; rr < 4; rr++) {
            int row = r + rr * 32;
            float4 v = make_float4(0.f, 0.f, 0.f, 0.f);
            if (i0 + row < N_NODES)
                v = *(const float4*)&g_h1[(size_t)(i0 + row) * F_IN + k0 + kc];
            As[kc + 0][row] = v.x; As[kc + 1][row] = v.y;
            As[kc + 2][row] = v.z; As[kc + 3][row] = v.w;
        }
        const float* bsrc = W2 + (size_t)k0 * C_OUT;
        #pragma unroll
        for (int i = 0; i < 5; i++) Bs[tid * 5 + i] = bsrc[tid * 5 + i];
        __syncthreads();
        #pragma unroll
        for (int kk = 0; kk < 16; kk++) {
            float a[8], b[5];
            *(float4*)&a[0] = *(float4*)&As[kk][rg * 8];
            *(float4*)&a[4] = *(float4*)&As[kk][rg * 8 + 4];
            #pragma unroll
            for (int i = 0; i < 5; i++) b[i] = Bs[kk * 40 + cg * 5 + i];
            #pragma unroll
            for (int r2 = 0; r2 < 8; r2++)
                #pragma unroll
                for (int c2 = 0; c2 < 5; c2++)
                    acc[r2][c2] += a[r2] * b[c2];
        }
        __syncthreads();
    }
    bool gvalid = (i0 + rg * 8) < N_NODES;
    #pragma unroll
    for (int r = 0; r < 8; r++) {
        int row = i0 + rg * 8 + r;
        if (row < N_NODES) {
            #pragma unroll
            for (int c = 0; c < 5; c++)
                g_Wh2[(size_t)row * C_OUT + cg * 5 + c] = acc[r][c];
        }
    }
    #pragma unroll
    for (int c = 0; c < 5; c++) {
        int col = cg * 5 + c;
        __half tmp[8];
        #pragma unroll
        for (int r2 = 0; r2 < 8; r2++) tmp[r2] = __float2half_rn(acc[r2][c]);
        if (gvalid)
            *(uint4*)&g_WhT2[(size_t)col * JP + i0 + rg * 8] = *(uint4*)tmp;
    }
}

// ---------------- kernel 6: layer-2 scores ----------------
__global__ void scores2_kernel(const float* __restrict__ a_src2,
                               const float* __restrict__ a_tgt2) {
    int gw = (blockIdx.x * blockDim.x + threadIdx.x) >> 5;
    int lane = threadIdx.x & 31;
    if (gw >= N_NODES) return;
    float w1 = g_Wh2[(size_t)gw * C_OUT + lane];
    float as1 = a_src2[lane], at1 = a_tgt2[lane];
    float w2 = 0.f, as2 = 0.f, at2 = 0.f;
    if (lane + 32 < C_OUT) {
        w2 = g_Wh2[(size_t)gw * C_OUT + lane + 32];
        as2 = a_src2[lane + 32]; at2 = a_tgt2[lane + 32];
    }
    float ss = w1 * as1 + w2 * as2;
    float st = w1 * at1 + w2 * at2;
    #pragma unroll
    for (int o = 16; o > 0; o >>= 1) {
        ss += __shfl_xor_sync(0xFFFFFFFFu, ss, o);
        st += __shfl_xor_sync(0xFFFFFFFFu, st, o);
    }
    if (lane == 0) {
        g_S2src[gw] = ss; g_E2i[gw] = expf(ss); g_F2i[gw] = expf(ALPHA * ss);
        g_st2h[gw] = __float2half_rn(st);
        g_e2h [gw] = __float2half_rn(expf(st));
        g_f2h [gw] = __float2half_rn(expf(ALPHA * st));
    }
}

// ---------------- launch ----------------
extern "C" void kernel_launch(void* const* d_in, const int* in_sizes, int n_in,
                              void* d_out, int out_size) {
    const float* x      = (const float*)d_in[0];
    const int*   adj    = (const int*)  d_in[1];
    const float* W1     = (const float*)d_in[2];
    const float* a_src1 = (const float*)d_in[3];
    const float* a_tgt1 = (const float*)d_in[4];
    const float* W2     = (const float*)d_in[5];
    const float* a_src2 = (const float*)d_in[6];
    const float* a_tgt2 = (const float*)d_in[7];
    float* out = (float*)d_out;

    pack_adj_kernel<<<(N_NODES * NW * 32) / 256, 256>>>(adj, out, (long)out_size);

    gemm1_kernel<<<dim3((N_NODES + 63) / 64, H1), 128>>>(x, W1);
    scores1_kernel<<<(H1 * N_NODES * 32 + 255) / 256, 256>>>(a_src1, a_tgt1);
    av_mma_kernel<8, 8, false><<<dim3(JP / 64, H1), 128>>>(nullptr);

    gemm2_kernel<<<(N_NODES + 127) / 128, 128>>>(W2);
    scores2_kernel<<<(N_NODES * 32 + 255) / 256, 256>>>(a_src2, a_tgt2);
    av_mma_kernel<5, 6, true><<<dim3(JP / 64, 2), 128>>>(nullptr);
    combine2_kernel<<<(N_NODES * C_OUT + 255) / 256, 256>>>(out);
}

// round 7
// speedup vs baseline: 4.9351x; 1.1465x over previous
#include <cuda_runtime.h>
#include <cuda_fp16.h>
#include <math.h>
#include <stdint.h>

// ---------------- problem constants ----------------
#define N_NODES 6000
#define JP      6016           // N padded to multiple of 64
#define F_IN    512
#define HID     64
#define H1      8
#define C_OUT   40
#define NW      188
#define ALPHA   0.2f
#define OUT_ADJ_OFF (N_NODES * C_OUT)
#define NT_FULL 94             // JP/64

// ---------------- device scratch ----------------
__device__ float    g_Wh  [H1 * N_NODES * HID];
__device__ __half   g_WhT [H1 * HID * (size_t)JP];
__device__ unsigned g_adjb[N_NODES * NW];
__device__ float    g_h1  [N_NODES * (H1 * HID)];
__device__ float    g_Wh2 [N_NODES * C_OUT];
__device__ __half   g_WhT2[HID * (size_t)JP];
__device__ float    g_part[4 * 6016 * 48];       // layer2 partials (cols 0..39, Z at 40)

__device__ float  g_Ssrc[H1 * N_NODES], g_Ei[H1 * N_NODES], g_Fi[H1 * N_NODES];
__device__ float  g_S2src[N_NODES], g_E2i[N_NODES], g_F2i[N_NODES];
// per-node j-side tables (half): st, d = exp(st)-exp(.2st), f = exp(.2st); zero in pad
__device__ __half g_st1h[H1 * JP], g_d1h[H1 * JP], g_f1h[H1 * JP];
__device__ __half g_st2h[JP],      g_d2h[JP],      g_f2h[JP];

// ---------------- helpers ----------------
__device__ __forceinline__ uint32_t smem_u32(const void* p) {
    uint32_t a;
    asm("{ .reg .u64 t; cvta.to.shared.u64 t, %1; cvt.u32.u64 %0, t; }" : "=r"(a) : "l"(p));
    return a;
}
__device__ __forceinline__ void mma_16816(float c[4], const uint32_t a[4], const uint32_t b[2]) {
    asm volatile(
        "mma.sync.aligned.m16n8k16.row.col.f32.f16.f16.f32 "
        "{%0,%1,%2,%3}, {%4,%5,%6,%7}, {%8,%9}, {%0,%1,%2,%3};"
        : "+f"(c[0]), "+f"(c[1]), "+f"(c[2]), "+f"(c[3])
        : "r"(a[0]), "r"(a[1]), "r"(a[2]), "r"(a[3]), "r"(b[0]), "r"(b[1]));
}
__device__ __forceinline__ void mma_tf32(float c[4], const uint32_t a[4], const uint32_t b[2]) {
    asm volatile(
        "mma.sync.aligned.m16n8k8.row.col.f32.tf32.tf32.f32 "
        "{%0,%1,%2,%3}, {%4,%5,%6,%7}, {%8,%9}, {%0,%1,%2,%3};"
        : "+f"(c[0]), "+f"(c[1]), "+f"(c[2]), "+f"(c[3])
        : "r"(a[0]), "r"(a[1]), "r"(a[2]), "r"(a[3]), "r"(b[0]), "r"(b[1]));
}
__device__ __forceinline__ void ldsm_x4(uint32_t& r0, uint32_t& r1, uint32_t& r2, uint32_t& r3,
                                        uint32_t addr) {
    asm volatile("ldmatrix.sync.aligned.m8n8.x4.shared.b16 {%0,%1,%2,%3}, [%4];"
                 : "=r"(r0), "=r"(r1), "=r"(r2), "=r"(r3) : "r"(addr));
}
__device__ __forceinline__ uint32_t tf32_of(float x) {
    uint32_t r;
    asm("cvt.rna.tf32.f32 %0, %1;" : "=r"(r) : "f"(x));
    return r;
}
#define CP_ASYNC16(dst, src) \
    asm volatile("cp.async.cg.shared.global [%0], [%1], 16;" :: "r"(dst), "l"(src))
#define CP_COMMIT() asm volatile("cp.async.commit_group;" ::: "memory")
#define CP_WAIT1()  asm volatile("cp.async.wait_group 1;" ::: "memory")
#define CP_WAIT0()  asm volatile("cp.async.wait_group 0;" ::: "memory")

// ---------------- kernel 1: pack adjacency + echo adj to output ----------------
__global__ void pack_adj_kernel(const int* __restrict__ adj,
                                float* __restrict__ outf, long out_size) {
    int gtid = blockIdx.x * blockDim.x + threadIdx.x;
    int warp = gtid >> 5, lane = gtid & 31;
    int row = warp / NW, wj = warp % NW;
    int j = wj * 32 + lane;
    int v = 0;
    if (j < N_NODES) {
        long idx = (long)row * N_NODES + j;
        v = adj[idx];
        long oi = (long)OUT_ADJ_OFF + idx;
        if (oi < out_size) outf[oi] = (float)v;
    }
    unsigned bits = __ballot_sync(0xFFFFFFFFu, v != 0);
    if (lane == 0) g_adjb[row * NW + wj] = bits;
}

// ---------------- kernel 2: Wh = x @ W1[h] on tf32 mma; emits Wh fp32 + WhT fp16 ----------------
// 256 threads = 8 warps (4 row-groups x 2 col-groups), block tile 128x64, K-stage 16.
__global__ void __launch_bounds__(256) gemm1_kernel(const float* __restrict__ x,
                                                    const float* __restrict__ W1) {
    __shared__ __align__(16) char sbuf[17408];
    float* As = (float*)sbuf;                 // [128][20]
    float* Bs = (float*)(sbuf + 10240);       // [16][72]
    __half* T = (__half*)sbuf;                // [64][136] reused after mainloop

    int h  = blockIdx.y;
    int i0 = blockIdx.x * 128;
    int tid = threadIdx.x;
    int lane = tid & 31, warp = tid >> 5;
    int wr = warp >> 1, wc = warp & 1;
    const float* W1h = W1 + (size_t)h * F_IN * HID;

    float acc[2][4][4];
    #pragma unroll
    for (int m = 0; m < 2; m++)
        #pragma unroll
        for (int n = 0; n < 4; n++)
            #pragma unroll
            for (int c = 0; c < 4; c++) acc[m][n][c] = 0.f;

    int sr = tid >> 1, skk = (tid & 1) * 8;          // A staging: row, k-offset
    int bkk = tid >> 4, bn0 = (tid & 15) * 4;        // B staging

    for (int k0 = 0; k0 < F_IN; k0 += 16) {
        // stage A (cvt to tf32)
        {
            float4 v0 = make_float4(0.f, 0.f, 0.f, 0.f), v1 = v0;
            if (i0 + sr < N_NODES) {
                const float* src = &x[(size_t)(i0 + sr) * F_IN + k0 + skk];
                v0 = *(const float4*)src;
                v1 = *(const float4*)(src + 4);
            }
            uint32_t* d = (uint32_t*)&As[sr * 20 + skk];
            d[0] = tf32_of(v0.x); d[1] = tf32_of(v0.y); d[2] = tf32_of(v0.z); d[3] = tf32_of(v0.w);
            d[4] = tf32_of(v1.x); d[5] = tf32_of(v1.y); d[6] = tf32_of(v1.z); d[7] = tf32_of(v1.w);
        }
        // stage B
        {
            float4 b = *(const float4*)&W1h[(size_t)(k0 + bkk) * HID + bn0];
            uint32_t* d = (uint32_t*)&Bs[bkk * 72 + bn0];
            d[0] = tf32_of(b.x); d[1] = tf32_of(b.y); d[2] = tf32_of(b.z); d[3] = tf32_of(b.w);
        }
        __syncthreads();

        #pragma unroll
        for (int s = 0; s < 2; s++) {
            int arow = wr * 32 + (lane >> 2);
            int akol = s * 8 + (lane & 3);
            uint32_t af[2][4];
            #pragma unroll
            for (int m = 0; m < 2; m++) {
                int base = (arow + m * 16) * 20 + akol;
                af[m][0] = __float_as_uint(As[base]);
                af[m][1] = __float_as_uint(As[base + 8 * 20]);
                af[m][2] = __float_as_uint(As[base + 4]);
                af[m][3] = __float_as_uint(As[base + 8 * 20 + 4]);
            }
            int bb = (s * 8 + (lane & 3)) * 72 + wc * 32 + (lane >> 2);
            uint32_t bf[4][2];
            #pragma unroll
            for (int n = 0; n < 4; n++) {
                bf[n][0] = __float_as_uint(Bs[bb + n * 8]);
                bf[n][1] = __float_as_uint(Bs[bb + n * 8 + 4 * 72]);
            }
            #pragma unroll
            for (int m = 0; m < 2; m++)
                #pragma unroll
                for (int n = 0; n < 4; n++)
                    mma_tf32(acc[m][n], af[m], bf[n]);
        }
        __syncthreads();
    }

    // epilogue: g_Wh fp32 + smem fp16 transpose
    int rl = wr * 32 + (lane >> 2);
    int cb = wc * 32 + (lane & 3) * 2;
    #pragma unroll
    for (int m = 0; m < 2; m++) {
        int r0 = rl + m * 16, r1 = r0 + 8;
        #pragma unroll
        for (int n = 0; n < 4; n++) {
            int c = cb + n * 8;
            if (i0 + r0 < N_NODES)
                *(float2*)&g_Wh[((size_t)h * N_NODES + i0 + r0) * HID + c] =
                    make_float2(acc[m][n][0], acc[m][n][1]);
            if (i0 + r1 < N_NODES)
                *(float2*)&g_Wh[((size_t)h * N_NODES + i0 + r1) * HID + c] =
                    make_float2(acc[m][n][2], acc[m][n][3]);
            T[(c + 0) * 136 + r0] = __float2half_rn(acc[m][n][0]);
            T[(c + 1) * 136 + r0] = __float2half_rn(acc[m][n][1]);
            T[(c + 0) * 136 + r1] = __float2half_rn(acc[m][n][2]);
            T[(c + 1) * 136 + r1] = __float2half_rn(acc[m][n][3]);
        }
    }
    __syncthreads();
    // FIXED writeback: 64 dims x 128 rows = 1024 chunks of 8 halves (4 per thread)
    #pragma unroll
    for (int q = 0; q < 4; q++) {
        int l = tid + 256 * q;               // 0..1023
        int d = l >> 4, o = (l & 15) * 8;    // dim 0..63, row-offset 0..120
        *(uint4*)&g_WhT[((size_t)h * HID + d) * JP + i0 + o] = *(uint4*)&T[d * 136 + o];
    }
}

// ---------------- kernel 3: per-node scores + tables (layer 1) ----------------
__global__ void scores1_kernel(const float* __restrict__ a_src,
                               const float* __restrict__ a_tgt) {
    int gw = (blockIdx.x * blockDim.x + threadIdx.x) >> 5;
    int lane = threadIdx.x & 31;
    if (gw >= H1 * N_NODES) return;
    int h = gw / N_NODES, n = gw % N_NODES;
    const float* wh = &g_Wh[((size_t)h * N_NODES + n) * HID];
    float w1 = wh[lane], w2 = wh[lane + 32];
    float ss = w1 * a_src[h * HID + lane] + w2 * a_src[h * HID + lane + 32];
    float st = w1 * a_tgt[h * HID + lane] + w2 * a_tgt[h * HID + lane + 32];
    #pragma unroll
    for (int o = 16; o > 0; o >>= 1) {
        ss += __shfl_xor_sync(0xFFFFFFFFu, ss, o);
        st += __shfl_xor_sync(0xFFFFFFFFu, st, o);
    }
    if (lane == 0) {
        g_Ssrc[gw] = ss; g_Ei[gw] = expf(ss); g_Fi[gw] = expf(ALPHA * ss);
        size_t hi = (size_t)h * JP + n;
        float e = expf(st), f = expf(ALPHA * st);
        g_st1h[hi] = __float2half_rn(st);
        g_d1h [hi] = __float2half_rn(e - f);
        g_f1h [hi] = __float2half_rn(f);
    }
}

// ---------------- fused masked-softmax AV on mma.sync ----------------
// 128 threads = 4 warps, 64 i-rows/block; Z via ones-column MMA; 5-op half2 build.
template<int NG, int NGL, bool L2K>
__global__ void __launch_bounds__(128, 5) av_mma_kernel(float* __restrict__ dummy) {
    __shared__ __align__(16) __half Bbuf[2][64 * 72];
    __shared__ __align__(16) __half stb[2][64];
    __shared__ __align__(16) __half db [2][64];
    __shared__ __align__(16) __half fb [2][64];

    int tid = threadIdx.x;
    int lane = tid & 31, warp = tid >> 5;
    int i0 = blockIdx.x * 64;

    const float *Ssrc, *Eiv, *Fiv;
    const __half *sth, *dhp, *fhp, *whT;
    int tbeg, tend;
    if (L2K) {
        Ssrc = g_S2src; Eiv = g_E2i; Fiv = g_F2i;
        sth = g_st2h; dhp = g_d2h; fhp = g_f2h;
        whT = g_WhT2;
        int y = blockIdx.y;
        tbeg = y * 24 - (y == 3 ? 1 : 0);
        tend = tbeg + (y < 2 ? 24 : 23);
    } else {
        int h = blockIdx.y;
        int hb = h * N_NODES;
        Ssrc = g_Ssrc + hb; Eiv = g_Ei + hb; Fiv = g_Fi + hb;
        size_t hj = (size_t)h * JP;
        sth = g_st1h + hj; dhp = g_d1h + hj; fhp = g_f1h + hj;
        whT = g_WhT + (size_t)h * HID * JP;
        tbeg = 0; tend = NT_FULL;
    }

    int r0 = i0 + warp * 16 + (lane >> 2);
    int rowc[2] = { min(r0, N_NODES - 1), min(r0 + 8, N_NODES - 1) };
    __half2 TH2[2], DE2[2], F2[2];
    #pragma unroll
    for (int rr = 0; rr < 2; rr++) {
        float ss = Ssrc[rowc[rr]], Ei = Eiv[rowc[rr]], Fi = Fiv[rowc[rr]];
        TH2[rr] = __half2half2(__float2half_rn(-ss));
        DE2[rr] = __half2half2(__float2half_rn(Ei - Fi));
        F2 [rr] = __half2half2(__float2half_rn(Fi));
    }
    int cb = (lane & 3) * 2;

    int nb = (lane & 7) | (((lane >> 4) & 1) << 3);
    int kb = ((lane >> 3) & 1) * 8;
    uint32_t bB[2] = { smem_u32(Bbuf[0]), smem_u32(Bbuf[1]) };
    uint32_t bST[2] = { smem_u32(stb[0]), smem_u32(stb[1]) };
    uint32_t bD[2]  = { smem_u32(db[0]),  smem_u32(db[1])  };
    uint32_t bF[2]  = { smem_u32(fb[0]),  smem_u32(fb[1])  };
    uint32_t lds_off = (uint32_t)(nb * 72 + kb) * 2;

    float acc[NG][4];
    float accz[4];
    #pragma unroll
    for (int g = 0; g < NG; g++)
        #pragma unroll
        for (int c = 0; c < 4; c++) acc[g][c] = 0.f;
    #pragma unroll
    for (int c = 0; c < 4; c++) accz[c] = 0.f;

    const uint32_t ONES2 = 0x3C003C00u;
    const uint32_t bz[2] = { ONES2, ONES2 };

    int NT = tend - tbeg;

    auto stage = [&](int t, int b) {
        int j0 = (tbeg + t) * 64;
        #pragma unroll
        for (int i2 = 0; i2 < 4; i2++) {
            int c = tid + 128 * i2;
            int n = c >> 3, o = c & 7;
            CP_ASYNC16(bB[b] + (uint32_t)(n * 144 + o * 16),
                       whT + (size_t)n * JP + j0 + o * 8);
        }
        if (tid >= 96 && tid < 120) {
            int a2 = tid - 96;
            int arr = a2 >> 3, ch = a2 & 7;
            const __half* src = (arr == 0 ? sth : arr == 1 ? dhp : fhp) + j0 + ch * 8;
            uint32_t dst = (arr == 0 ? bST[b] : arr == 1 ? bD[b] : bF[b]) + (uint32_t)ch * 16;
            CP_ASYNC16(dst, src);
        }
    };

    stage(0, 0);
    CP_COMMIT();

    for (int t = 0; t < NT; t++) {
        int b = t & 1;
        if (t + 1 < NT) { stage(t + 1, (t + 1) & 1); CP_COMMIT(); CP_WAIT1(); }
        else            { CP_COMMIT(); CP_WAIT0(); }
        __syncthreads();

        int tg = tbeg + t;
        uint2 aw[2];
        aw[0] = *(const uint2*)&g_adjb[(size_t)rowc[0] * NW + 2 * tg];
        aw[1] = *(const uint2*)&g_adjb[(size_t)rowc[1] * NW + 2 * tg];

        #pragma unroll
        for (int ks = 0; ks < 4; ks++) {
            int jb = ks * 16 + cb;
            __half2 st2a = *(__half2*)&stb[b][jb];
            __half2 st2b = *(__half2*)&stb[b][jb + 8];
            __half2 d2a  = *(__half2*)&db[b][jb];
            __half2 d2b  = *(__half2*)&db[b][jb + 8];
            __half2 f2a  = *(__half2*)&fb[b][jb];
            __half2 f2b  = *(__half2*)&fb[b][jb + 8];

            uint32_t a[4];
            #pragma unroll
            for (int rr = 0; rr < 2; rr++) {
                unsigned word = (ks < 2) ? aw[rr].x : aw[rr].y;
                unsigned ta = word >> (((ks & 1) << 4) + cb);
                unsigned tbits = ta >> 8;
                uint32_t ma = ((ta & 1u) ? 0x3C00u : 0u) | ((ta & 2u) ? 0x3C000000u : 0u);
                uint32_t mb = ((tbits & 1u) ? 0x3C00u : 0u) | ((tbits & 2u) ? 0x3C000000u : 0u);

                __half2 m2  = __hgt2(st2a, TH2[rr]);
                __half2 si  = __hfma2(m2, DE2[rr], F2[rr]);
                __half2 sj  = __hfma2(m2, d2a, f2a);
                __half2 wa  = __hmul2(__hmul2(si, sj), *(__half2*)&ma);

                __half2 m2b = __hgt2(st2b, TH2[rr]);
                __half2 sib = __hfma2(m2b, DE2[rr], F2[rr]);
                __half2 sjb = __hfma2(m2b, d2b, f2b);
                __half2 wbv = __hmul2(__hmul2(sib, sjb), *(__half2*)&mb);

                a[rr]     = *(uint32_t*)&wa;
                a[rr + 2] = *(uint32_t*)&wbv;
            }

            uint32_t bf[NGL][2];
            #pragma unroll
            for (int p = 0; p < NGL / 2; p++)
                ldsm_x4(bf[2 * p][0], bf[2 * p][1], bf[2 * p + 1][0], bf[2 * p + 1][1],
                        bB[b] + lds_off + (uint32_t)(p * 16 * 144 + ks * 32));

            #pragma unroll
            for (int g = 0; g < NG; g++)
                mma_16816(acc[g], a, bf[g]);
            mma_16816(accz, a, bz);
        }
        __syncthreads();
    }

    // ---- epilogue ----
    #pragma unroll
    for (int rr = 0; rr < 2; rr++) {
        int row = r0 + rr * 8;
        if (row >= N_NODES) continue;
        if (L2K) {
            size_t base = ((size_t)blockIdx.y * 6016 + row) * 48;
            #pragma unroll
            for (int g = 0; g < NG; g++)
                *(float2*)&g_part[base + g * 8 + cb] =
                    make_float2(acc[g][rr * 2], acc[g][rr * 2 + 1]);
            if (cb == 0) g_part[base + 40] = accz[rr * 2];
        } else {
            float invZ = 1.0f / accz[rr * 2];
            int h = blockIdx.y;
            #pragma unroll
            for (int g = 0; g < NG; g++) {
                float v0 = acc[g][rr * 2]     * invZ;
                float v1 = acc[g][rr * 2 + 1] * invZ;
                v0 = v0 > 0.f ? v0 : expm1f(v0);
                v1 = v1 > 0.f ? v1 : expm1f(v1);
                *(float2*)&g_h1[(size_t)row * (H1 * HID) + h * HID + g * 8 + cb] =
                    make_float2(v0, v1);
            }
        }
    }
}

// ---------------- layer-2 partial combine (4 parts) ----------------
__global__ void combine2_kernel(float* __restrict__ out) {
    int idx = blockIdx.x * blockDim.x + threadIdx.x;
    if (idx >= N_NODES * C_OUT) return;
    int row = idx / C_OUT, c = idx - row * C_OUT;
    float num = 0.f, z = 0.f;
    #pragma unroll
    for (int y = 0; y < 4; y++) {
        size_t b = ((size_t)y * 6016 + row) * 48;
        num += g_part[b + c];
        z   += g_part[b + 40];
    }
    out[idx] = num / z;
}

// ---------------- kernel 5: Wh2 = h1 @ W2; emits Wh2 fp32 + WhT2 fp16 ----------------
__global__ void __launch_bounds__(128) gemm2_kernel(const float* __restrict__ W2) {
    __shared__ float As[16][128];
    __shared__ float Bs[16 * 40];
    int i0 = blockIdx.x * 128;
    int tid = threadIdx.x;
    int cg = tid & 7, rg = tid >> 3;
    float acc[8][5];
    #pragma unroll
    for (int r = 0; r < 8; r++)
        #pragma unroll
        for (int c = 0; c < 5; c++) acc[r][c] = 0.f;

    for (int k0 = 0; k0 < F_IN; k0 += 16) {
        int r  = tid >> 2;
        int kc = (tid & 3) * 4;
        #pragma unroll
        for (int rr = 0; rr < 4; rr++) {
            int row = r + rr * 32;
            float4 v = make_float4(0.f, 0.f, 0.f, 0.f);
            if (i0 + row < N_NODES)
                v = *(const float4*)&g_h1[(size_t)(i0 + row) * F_IN + k0 + kc];
            As[kc + 0][row] = v.x; As[kc + 1][row] = v.y;
            As[kc + 2][row] = v.z; As[kc + 3][row] = v.w;
        }
        const float* bsrc = W2 + (size_t)k0 * C_OUT;
        #pragma unroll
        for (int i = 0; i < 5; i++) Bs[tid * 5 + i] = bsrc[tid * 5 + i];
        __syncthreads();
        #pragma unroll
        for (int kk = 0; kk < 16; kk++) {
            float a[8], b[5];
            *(float4*)&a[0] = *(float4*)&As[kk][rg * 8];
            *(float4*)&a[4] = *(float4*)&As[kk][rg * 8 + 4];
            #pragma unroll
            for (int i = 0; i < 5; i++) b[i] = Bs[kk * 40 + cg * 5 + i];
            #pragma unroll
            for (int r2 = 0; r2 < 8; r2++)
                #pragma unroll
                for (int c2 = 0; c2 < 5; c2++)
                    acc[r2][c2] += a[r2] * b[c2];
        }
        __syncthreads();
    }
    bool gvalid = (i0 + rg * 8) < N_NODES;
    #pragma unroll
    for (int r = 0; r < 8; r++) {
        int row = i0 + rg * 8 + r;
        if (row < N_NODES) {
            #pragma unroll
            for (int c = 0; c < 5; c++)
                g_Wh2[(size_t)row * C_OUT + cg * 5 + c] = acc[r][c];
        }
    }
    #pragma unroll
    for (int c = 0; c < 5; c++) {
        int col = cg * 5 + c;
        __half tmp[8];
        #pragma unroll
        for (int r2 = 0; r2 < 8; r2++) tmp[r2] = __float2half_rn(acc[r2][c]);
        if (gvalid)
            *(uint4*)&g_WhT2[(size_t)col * JP + i0 + rg * 8] = *(uint4*)tmp;
    }
}

// ---------------- kernel 6: layer-2 scores ----------------
__global__ void scores2_kernel(const float* __restrict__ a_src2,
                               const float* __restrict__ a_tgt2) {
    int gw = (blockIdx.x * blockDim.x + threadIdx.x) >> 5;
    int lane = threadIdx.x & 31;
    if (gw >= N_NODES) return;
    float w1 = g_Wh2[(size_t)gw * C_OUT + lane];
    float as1 = a_src2[lane], at1 = a_tgt2[lane];
    float w2 = 0.f, as2 = 0.f, at2 = 0.f;
    if (lane + 32 < C_OUT) {
        w2 = g_Wh2[(size_t)gw * C_OUT + lane + 32];
        as2 = a_src2[lane + 32]; at2 = a_tgt2[lane + 32];
    }
    float ss = w1 * as1 + w2 * as2;
    float st = w1 * at1 + w2 * at2;
    #pragma unroll
    for (int o = 16; o > 0; o >>= 1) {
        ss += __shfl_xor_sync(0xFFFFFFFFu, ss, o);
        st += __shfl_xor_sync(0xFFFFFFFFu, st, o);
    }
    if (lane == 0) {
        g_S2src[gw] = ss; g_E2i[gw] = expf(ss); g_F2i[gw] = expf(ALPHA * ss);
        float e = expf(st), f = expf(ALPHA * st);
        g_st2h[gw] = __float2half_rn(st);
        g_d2h [gw] = __float2half_rn(e - f);
        g_f2h [gw] = __float2half_rn(f);
    }
}

// ---------------- launch ----------------
extern "C" void kernel_launch(void* const* d_in, const int* in_sizes, int n_in,
                              void* d_out, int out_size) {
    const float* x      = (const float*)d_in[0];
    const int*   adj    = (const int*)  d_in[1];
    const float* W1     = (const float*)d_in[2];
    const float* a_src1 = (const float*)d_in[3];
    const float* a_tgt1 = (const float*)d_in[4];
    const float* W2     = (const float*)d_in[5];
    const float* a_src2 = (const float*)d_in[6];
    const float* a_tgt2 = (const float*)d_in[7];
    float* out = (float*)d_out;

    pack_adj_kernel<<<(N_NODES * NW * 32) / 256, 256>>>(adj, out, (long)out_size);

    gemm1_kernel<<<dim3((N_NODES + 127) / 128, H1), 256>>>(x, W1);
    scores1_kernel<<<(H1 * N_NODES * 32 + 255) / 256, 256>>>(a_src1, a_tgt1);
    av_mma_kernel<8, 8, false><<<dim3(JP / 64, H1), 128>>>(nullptr);

    gemm2_kernel<<<(N_NODES + 127) / 128, 128>>>(W2);
    scores2_kernel<<<(N_NODES * 32 + 255) / 256, 256>>>(a_src2, a_tgt2);
    av_mma_kernel<5, 6, true><<<dim3(JP / 64, 4), 128>>>(nullptr);
    combine2_kernel<<<(N_NODES * C_OUT + 255) / 256, 256>>>(out);
}

// round 8
// speedup vs baseline: 5.4286x; 1.1000x over previous
#include <cuda_runtime.h>
#include <cuda_fp16.h>
#include <math.h>
#include <stdint.h>

// ---------------- problem constants ----------------
#define N_NODES 6000
#define JP      6016           // N padded to multiple of 64
#define F_IN    512
#define HID     64
#define H1      8
#define C_OUT   40
#define NW      188
#define ALPHA   0.2f
#define OUT_ADJ_OFF (N_NODES * C_OUT)
#define NT_FULL 94             // JP/64

// ---------------- device scratch ----------------
__device__ float    g_Wh  [H1 * N_NODES * HID];
__device__ __half   g_WhT [H1 * HID * (size_t)JP];
__device__ unsigned g_adjb[N_NODES * NW];
__device__ float    g_h1  [N_NODES * (H1 * HID)];
__device__ float    g_Wh2 [N_NODES * C_OUT];
__device__ __half   g_WhT2[HID * (size_t)JP];
__device__ float    g_part[8 * 6016 * 48];       // layer2 partials (cols 0..39, Z at 40)

__device__ float  g_Ssrc[H1 * N_NODES], g_Ei[H1 * N_NODES], g_Fi[H1 * N_NODES];
__device__ float  g_S2src[N_NODES], g_E2i[N_NODES], g_F2i[N_NODES];
// packed per-j tables: entry (j/2) = { st2, d2, f2, pad } halves; zero in pad region
__device__ uint4  g_pk1[H1 * (JP / 2)];
__device__ uint4  g_pk2[JP / 2];

// ---------------- helpers ----------------
__device__ __forceinline__ uint32_t smem_u32(const void* p) {
    uint32_t a;
    asm("{ .reg .u64 t; cvta.to.shared.u64 t, %1; cvt.u32.u64 %0, t; }" : "=r"(a) : "l"(p));
    return a;
}
__device__ __forceinline__ void mma_16816(float c[4], const uint32_t a[4], const uint32_t b[2]) {
    asm volatile(
        "mma.sync.aligned.m16n8k16.row.col.f32.f16.f16.f32 "
        "{%0,%1,%2,%3}, {%4,%5,%6,%7}, {%8,%9}, {%0,%1,%2,%3};"
        : "+f"(c[0]), "+f"(c[1]), "+f"(c[2]), "+f"(c[3])
        : "r"(a[0]), "r"(a[1]), "r"(a[2]), "r"(a[3]), "r"(b[0]), "r"(b[1]));
}
__device__ __forceinline__ void mma_tf32(float c[4], const uint32_t a[4], const uint32_t b[2]) {
    asm volatile(
        "mma.sync.aligned.m16n8k8.row.col.f32.tf32.tf32.f32 "
        "{%0,%1,%2,%3}, {%4,%5,%6,%7}, {%8,%9}, {%0,%1,%2,%3};"
        : "+f"(c[0]), "+f"(c[1]), "+f"(c[2]), "+f"(c[3])
        : "r"(a[0]), "r"(a[1]), "r"(a[2]), "r"(a[3]), "r"(b[0]), "r"(b[1]));
}
__device__ __forceinline__ void ldsm_x4(uint32_t& r0, uint32_t& r1, uint32_t& r2, uint32_t& r3,
                                        uint32_t addr) {
    asm volatile("ldmatrix.sync.aligned.m8n8.x4.shared.b16 {%0,%1,%2,%3}, [%4];"
                 : "=r"(r0), "=r"(r1), "=r"(r2), "=r"(r3) : "r"(addr));
}
__device__ __forceinline__ uint32_t tf32_of(float x) {
    uint32_t r;
    asm("cvt.rna.tf32.f32 %0, %1;" : "=r"(r) : "f"(x));
    return r;
}
#define CP_ASYNC16(dst, src) \
    asm volatile("cp.async.cg.shared.global [%0], [%1], 16;" :: "r"(dst), "l"(src))
#define CP_COMMIT() asm volatile("cp.async.commit_group;" ::: "memory")
#define CP_WAIT1()  asm volatile("cp.async.wait_group 1;" ::: "memory")
#define CP_WAIT0()  asm volatile("cp.async.wait_group 0;" ::: "memory")

// ---------------- kernel 1: pack adjacency + echo adj to output ----------------
__global__ void pack_adj_kernel(const int* __restrict__ adj,
                                float* __restrict__ outf, long out_size) {
    int gtid = blockIdx.x * blockDim.x + threadIdx.x;
    int warp = gtid >> 5, lane = gtid & 31;
    int row = warp / NW, wj = warp % NW;
    int j = wj * 32 + lane;
    int v = 0;
    if (j < N_NODES) {
        long idx = (long)row * N_NODES + j;
        v = adj[idx];
        long oi = (long)OUT_ADJ_OFF + idx;
        if (oi < out_size) outf[oi] = (float)v;
    }
    unsigned bits = __ballot_sync(0xFFFFFFFFu, v != 0);
    if (lane == 0) g_adjb[row * NW + wj] = bits;
}

// ---------------- kernel 2: Wh = x @ W1[h] on tf32 mma; emits Wh fp32 + WhT fp16 ----------------
__global__ void __launch_bounds__(256) gemm1_kernel(const float* __restrict__ x,
                                                    const float* __restrict__ W1) {
    __shared__ __align__(16) char sbuf[17408];
    float* As = (float*)sbuf;                 // [128][20]
    float* Bs = (float*)(sbuf + 10240);       // [16][72]
    __half* T = (__half*)sbuf;                // [64][136] reused after mainloop

    int h  = blockIdx.y;
    int i0 = blockIdx.x * 128;
    int tid = threadIdx.x;
    int lane = tid & 31, warp = tid >> 5;
    int wr = warp >> 1, wc = warp & 1;
    const float* W1h = W1 + (size_t)h * F_IN * HID;

    float acc[2][4][4];
    #pragma unroll
    for (int m = 0; m < 2; m++)
        #pragma unroll
        for (int n = 0; n < 4; n++)
            #pragma unroll
            for (int c = 0; c < 4; c++) acc[m][n][c] = 0.f;

    int sr = tid >> 1, skk = (tid & 1) * 8;
    int bkk = tid >> 4, bn0 = (tid & 15) * 4;

    for (int k0 = 0; k0 < F_IN; k0 += 16) {
        {
            float4 v0 = make_float4(0.f, 0.f, 0.f, 0.f), v1 = v0;
            if (i0 + sr < N_NODES) {
                const float* src = &x[(size_t)(i0 + sr) * F_IN + k0 + skk];
                v0 = *(const float4*)src;
                v1 = *(const float4*)(src + 4);
            }
            uint32_t* d = (uint32_t*)&As[sr * 20 + skk];
            d[0] = tf32_of(v0.x); d[1] = tf32_of(v0.y); d[2] = tf32_of(v0.z); d[3] = tf32_of(v0.w);
            d[4] = tf32_of(v1.x); d[5] = tf32_of(v1.y); d[6] = tf32_of(v1.z); d[7] = tf32_of(v1.w);
        }
        {
            float4 b = *(const float4*)&W1h[(size_t)(k0 + bkk) * HID + bn0];
            uint32_t* d = (uint32_t*)&Bs[bkk * 72 + bn0];
            d[0] = tf32_of(b.x); d[1] = tf32_of(b.y); d[2] = tf32_of(b.z); d[3] = tf32_of(b.w);
        }
        __syncthreads();

        #pragma unroll
        for (int s = 0; s < 2; s++) {
            int arow = wr * 32 + (lane >> 2);
            int akol = s * 8 + (lane & 3);
            uint32_t af[2][4];
            #pragma unroll
            for (int m = 0; m < 2; m++) {
                int base = (arow + m * 16) * 20 + akol;
                af[m][0] = __float_as_uint(As[base]);
                af[m][1] = __float_as_uint(As[base + 8 * 20]);
                af[m][2] = __float_as_uint(As[base + 4]);
                af[m][3] = __float_as_uint(As[base + 8 * 20 + 4]);
            }
            int bb = (s * 8 + (lane & 3)) * 72 + wc * 32 + (lane >> 2);
            uint32_t bf[4][2];
            #pragma unroll
            for (int n = 0; n < 4; n++) {
                bf[n][0] = __float_as_uint(Bs[bb + n * 8]);
                bf[n][1] = __float_as_uint(Bs[bb + n * 8 + 4 * 72]);
            }
            #pragma unroll
            for (int m = 0; m < 2; m++)
                #pragma unroll
                for (int n = 0; n < 4; n++)
                    mma_tf32(acc[m][n], af[m], bf[n]);
        }
        __syncthreads();
    }

    int rl = wr * 32 + (lane >> 2);
    int cb = wc * 32 + (lane & 3) * 2;
    #pragma unroll
    for (int m = 0; m < 2; m++) {
        int r0 = rl + m * 16, r1 = r0 + 8;
        #pragma unroll
        for (int n = 0; n < 4; n++) {
            int c = cb + n * 8;
            if (i0 + r0 < N_NODES)
                *(float2*)&g_Wh[((size_t)h * N_NODES + i0 + r0) * HID + c] =
                    make_float2(acc[m][n][0], acc[m][n][1]);
            if (i0 + r1 < N_NODES)
                *(float2*)&g_Wh[((size_t)h * N_NODES + i0 + r1) * HID + c] =
                    make_float2(acc[m][n][2], acc[m][n][3]);
            T[(c + 0) * 136 + r0] = __float2half_rn(acc[m][n][0]);
            T[(c + 1) * 136 + r0] = __float2half_rn(acc[m][n][1]);
            T[(c + 0) * 136 + r1] = __float2half_rn(acc[m][n][2]);
            T[(c + 1) * 136 + r1] = __float2half_rn(acc[m][n][3]);
        }
    }
    __syncthreads();
    #pragma unroll
    for (int q = 0; q < 4; q++) {
        int l = tid + 256 * q;               // 0..1023
        int d = l >> 4, o = (l & 15) * 8;
        *(uint4*)&g_WhT[((size_t)h * HID + d) * JP + i0 + o] = *(uint4*)&T[d * 136 + o];
    }
}

// ---------------- kernel 3: per-node scores + packed tables (layer 1) ----------------
__global__ void scores1_kernel(const float* __restrict__ a_src,
                               const float* __restrict__ a_tgt) {
    int gw = (blockIdx.x * blockDim.x + threadIdx.x) >> 5;
    int lane = threadIdx.x & 31;
    if (gw >= H1 * N_NODES) return;
    int h = gw / N_NODES, n = gw % N_NODES;
    const float* wh = &g_Wh[((size_t)h * N_NODES + n) * HID];
    float w1 = wh[lane], w2 = wh[lane + 32];
    float ss = w1 * a_src[h * HID + lane] + w2 * a_src[h * HID + lane + 32];
    float st = w1 * a_tgt[h * HID + lane] + w2 * a_tgt[h * HID + lane + 32];
    #pragma unroll
    for (int o = 16; o > 0; o >>= 1) {
        ss += __shfl_xor_sync(0xFFFFFFFFu, ss, o);
        st += __shfl_xor_sync(0xFFFFFFFFu, st, o);
    }
    if (lane == 0) {
        g_Ssrc[gw] = ss; g_Ei[gw] = expf(ss); g_Fi[gw] = expf(ALPHA * ss);
        float e = expf(st), f = expf(ALPHA * st);
        __half* pk = (__half*)&g_pk1[(size_t)h * (JP / 2) + (n >> 1)];
        int o = n & 1;
        pk[0 + o] = __float2half_rn(st);
        pk[2 + o] = __float2half_rn(e - f);
        pk[4 + o] = __float2half_rn(f);
    }
}

// ---------------- fused masked-softmax AV on mma.sync ----------------
// 128 threads = 4 warps, 32 rows/warp (2 row-groups) -> 128 rows/block.
// Triple-buffered cp.async (1 sync/tile); packed per-j scalars (2x LDS.128/ks);
// B fragments shared by both row groups; Z via ones-column MMA.
template<int NG, int NGL, bool L2K>
__global__ void __launch_bounds__(128, 3) av_mma_kernel(float* __restrict__ dummy) {
    __shared__ __align__(16) __half Bbuf[3][64 * 72];
    __shared__ __align__(16) uint4  Pbuf[3][32];

    int tid = threadIdx.x;
    int lane = tid & 31, warp = tid >> 5;
    int i0 = blockIdx.x * 128;

    const float *Ssrc, *Eiv, *Fiv;
    const uint4* pk;
    const __half* whT;
    int tbeg, NT;
    if (L2K) {
        Ssrc = g_S2src; Eiv = g_E2i; Fiv = g_F2i;
        pk = g_pk2; whT = g_WhT2;
        int y = blockIdx.y;
        tbeg = (y < 6) ? y * 12 : 72 + (y - 6) * 11;
        NT   = (y < 6) ? 12 : 11;
    } else {
        int h = blockIdx.y;
        int hb = h * N_NODES;
        Ssrc = g_Ssrc + hb; Eiv = g_Ei + hb; Fiv = g_Fi + hb;
        pk = g_pk1 + (size_t)h * (JP / 2);
        whT = g_WhT + (size_t)h * HID * JP;
        tbeg = 0; NT = NT_FULL;
    }

    // 4 row slots: r0 + {0,8,16,24}
    int r0 = i0 + warp * 32 + (lane >> 2);
    int rowc[4];
    __half2 TH2[4], DE2[4], F2[4];
    #pragma unroll
    for (int s = 0; s < 4; s++) {
        rowc[s] = min(r0 + s * 8, N_NODES - 1);
        float ss = Ssrc[rowc[s]], Ei = Eiv[rowc[s]], Fi = Fiv[rowc[s]];
        TH2[s] = __half2half2(__float2half_rn(-ss));
        DE2[s] = __half2half2(__float2half_rn(Ei - Fi));
        F2 [s] = __half2half2(__float2half_rn(Fi));
    }
    int c4 = lane & 3, cb = c4 * 2;

    int nb = (lane & 7) | (((lane >> 4) & 1) << 3);
    int kb = ((lane >> 3) & 1) * 8;
    uint32_t bB[3] = { smem_u32(Bbuf[0]), smem_u32(Bbuf[1]), smem_u32(Bbuf[2]) };
    uint32_t lds_off = (uint32_t)(nb * 72 + kb) * 2;

    float acc[2][NG][4];
    float accz[2][4];
    #pragma unroll
    for (int g = 0; g < 2; g++) {
        #pragma unroll
        for (int n = 0; n < NG; n++)
            #pragma unroll
            for (int c = 0; c < 4; c++) acc[g][n][c] = 0.f;
        #pragma unroll
        for (int c = 0; c < 4; c++) accz[g][c] = 0.f;
    }

    const uint32_t ONES2 = 0x3C003C00u;
    const uint32_t bz[2] = { ONES2, ONES2 };

    auto stage = [&](int t, int b) {
        int j0 = (tbeg + t) * 64;
        #pragma unroll
        for (int i2 = 0; i2 < 4; i2++) {
            int c = tid + 128 * i2;
            int n = c >> 3, o = c & 7;
            CP_ASYNC16(bB[b] + (uint32_t)(n * 144 + o * 16),
                       whT + (size_t)n * JP + j0 + o * 8);
        }
        if (tid >= 96) {
            int e = tid - 96;                  // 0..31
            CP_ASYNC16(smem_u32(&Pbuf[b][e]), pk + (j0 >> 1) + e);
        }
    };

    stage(0, 0); CP_COMMIT();
    if (NT > 1) { stage(1, 1); CP_COMMIT(); }

    // adjacency for tile 0
    uint2 aw_cur[4], aw_nxt[4];
    #pragma unroll
    for (int s = 0; s < 4; s++)
        aw_cur[s] = *(const uint2*)&g_adjb[(size_t)rowc[s] * NW + 2 * tbeg];

    for (int t = 0; t < NT; t++) {
        int b = t % 3;
        if (t + 1 < NT) CP_WAIT1(); else CP_WAIT0();
        __syncthreads();
        if (t + 2 < NT) { stage(t + 2, (t + 2) % 3); CP_COMMIT(); }

        // prefetch adjacency for next tile
        if (t + 1 < NT) {
            #pragma unroll
            for (int s = 0; s < 4; s++)
                aw_nxt[s] = *(const uint2*)&g_adjb[(size_t)rowc[s] * NW + 2 * (tbeg + t + 1)];
        }

        #pragma unroll
        for (int ks = 0; ks < 4; ks++) {
            uint4 p0 = Pbuf[b][ks * 8 + c4];
            uint4 p1 = Pbuf[b][ks * 8 + c4 + 4];
            __half2 stA = *(__half2*)&p0.x, dA = *(__half2*)&p0.y, fA = *(__half2*)&p0.z;
            __half2 stB = *(__half2*)&p1.x, dB = *(__half2*)&p1.y, fB = *(__half2*)&p1.z;

            // B fragments once, shared by both row groups
            uint32_t bf[NGL][2];
            #pragma unroll
            for (int p = 0; p < NGL / 2; p++)
                ldsm_x4(bf[2 * p][0], bf[2 * p][1], bf[2 * p + 1][0], bf[2 * p + 1][1],
                        bB[b] + lds_off + (uint32_t)(p * 16 * 144 + ks * 32));

            int sh = ((ks & 1) << 4) + cb;
            #pragma unroll
            for (int g = 0; g < 2; g++) {
                uint32_t a[4];
                #pragma unroll
                for (int rr = 0; rr < 2; rr++) {
                    int s = g * 2 + rr;
                    unsigned word = (ks < 2) ? aw_cur[s].x : aw_cur[s].y;
                    unsigned ta = word >> sh;
                    unsigned tb2 = ta >> 8;
                    uint32_t ma = (ta  & 1u) * 0x3C00u + (ta  & 2u) * 0x1E000000u;
                    uint32_t mb = (tb2 & 1u) * 0x3C00u + (tb2 & 2u) * 0x1E000000u;

                    __half2 m2  = __hgt2(stA, TH2[s]);
                    __half2 si  = __hfma2(m2, DE2[s], F2[s]);
                    __half2 sj  = __hfma2(m2, dA, fA);
                    __half2 wa  = __hmul2(__hmul2(si, sj), *(__half2*)&ma);

                    __half2 m2b = __hgt2(stB, TH2[s]);
                    __half2 sib = __hfma2(m2b, DE2[s], F2[s]);
                    __half2 sjb = __hfma2(m2b, dB, fB);
                    __half2 wbv = __hmul2(__hmul2(sib, sjb), *(__half2*)&mb);

                    a[rr]     = *(uint32_t*)&wa;
                    a[rr + 2] = *(uint32_t*)&wbv;
                }
                #pragma unroll
                for (int n = 0; n < NG; n++)
                    mma_16816(acc[g][n], a, bf[n]);
                mma_16816(accz[g], a, bz);
            }
        }
        #pragma unroll
        for (int s = 0; s < 4; s++) aw_cur[s] = aw_nxt[s];
    }

    // ---- epilogue ----
    #pragma unroll
    for (int g = 0; g < 2; g++) {
        #pragma unroll
        for (int rr = 0; rr < 2; rr++) {
            int row = r0 + (g * 2 + rr) * 8;
            if (row >= N_NODES) continue;
            if (L2K) {
                size_t base = ((size_t)blockIdx.y * 6016 + row) * 48;
                #pragma unroll
                for (int n = 0; n < NG; n++)
                    *(float2*)&g_part[base + n * 8 + cb] =
                        make_float2(acc[g][n][rr * 2], acc[g][n][rr * 2 + 1]);
                if (cb == 0) g_part[base + 40] = accz[g][rr * 2];
            } else {
                float invZ = 1.0f / accz[g][rr * 2];
                int h = blockIdx.y;
                #pragma unroll
                for (int n = 0; n < NG; n++) {
                    float v0 = acc[g][n][rr * 2]     * invZ;
                    float v1 = acc[g][n][rr * 2 + 1] * invZ;
                    v0 = v0 > 0.f ? v0 : expm1f(v0);
                    v1 = v1 > 0.f ? v1 : expm1f(v1);
                    *(float2*)&g_h1[(size_t)row * (H1 * HID) + h * HID + n * 8 + cb] =
                        make_float2(v0, v1);
                }
            }
        }
    }
}

// ---------------- layer-2 partial combine (8 parts) ----------------
__global__ void combine2_kernel(float* __restrict__ out) {
    int idx = blockIdx.x * blockDim.x + threadIdx.x;
    if (idx >= N_NODES * C_OUT) return;
    int row = idx / C_OUT, c = idx - row * C_OUT;
    float num = 0.f, z = 0.f;
    #pragma unroll
    for (int y = 0; y < 8; y++) {
        size_t b = ((size_t)y * 6016 + row) * 48;
        num += g_part[b + c];
        z   += g_part[b + 40];
    }
    out[idx] = num / z;
}

// ---------------- kernel 5: Wh2 = h1 @ W2; emits Wh2 fp32 + WhT2 fp16 ----------------
__global__ void __launch_bounds__(128) gemm2_kernel(const float* __restrict__ W2) {
    __shared__ float As[16][128];
    __shared__ float Bs[16 * 40];
    int i0 = blockIdx.x * 128;
    int tid = threadIdx.x;
    int cg = tid & 7, rg = tid >> 3;
    float acc[8][5];
    #pragma unroll
    for (int r = 0; r < 8; r++)
        #pragma unroll
        for (int c = 0; c < 5; c++) acc[r][c] = 0.f;

    for (int k0 = 0; k0 < F_IN; k0 += 16) {
        int r  = tid >> 2;
        int kc = (tid & 3) * 4;
        #pragma unroll
        for (int rr = 0; rr < 4; rr++) {
            int row = r + rr * 32;
            float4 v = make_float4(0.f, 0.f, 0.f, 0.f);
            if (i0 + row < N_NODES)
                v = *(const float4*)&g_h1[(size_t)(i0 + row) * F_IN + k0 + kc];
            As[kc + 0][row] = v.x; As[kc + 1][row] = v.y;
            As[kc + 2][row] = v.z; As[kc + 3][row] = v.w;
        }
        const float* bsrc = W2 + (size_t)k0 * C_OUT;
        #pragma unroll
        for (int i = 0; i < 5; i++) Bs[tid * 5 + i] = bsrc[tid * 5 + i];
        __syncthreads();
        #pragma unroll
        for (int kk = 0; kk < 16; kk++) {
            float a[8], b[5];
            *(float4*)&a[0] = *(float4*)&As[kk][rg * 8];
            *(float4*)&a[4] = *(float4*)&As[kk][rg * 8 + 4];
            #pragma unroll
            for (int i = 0; i < 5; i++) b[i] = Bs[kk * 40 + cg * 5 + i];
            #pragma unroll
            for (int r2 = 0; r2 < 8; r2++)
                #pragma unroll
                for (int c2 = 0; c2 < 5; c2++)
                    acc[r2][c2] += a[r2] * b[c2];
        }
        __syncthreads();
    }
    bool gvalid = (i0 + rg * 8) < N_NODES;
    #pragma unroll
    for (int r = 0; r < 8; r++) {
        int row = i0 + rg * 8 + r;
        if (row < N_NODES) {
            #pragma unroll
            for (int c = 0; c < 5; c++)
                g_Wh2[(size_t)row * C_OUT + cg * 5 + c] = acc[r][c];
        }
    }
    #pragma unroll
    for (int c = 0; c < 5; c++) {
        int col = cg * 5 + c;
        __half tmp[8];
        #pragma unroll
        for (int r2 = 0; r2 < 8; r2++) tmp[r2] = __float2half_rn(acc[r2][c]);
        if (gvalid)
            *(uint4*)&g_WhT2[(size_t)col * JP + i0 + rg * 8] = *(uint4*)tmp;
    }
}

// ---------------- kernel 6: layer-2 scores (packed table) ----------------
__global__ void scores2_kernel(const float* __restrict__ a_src2,
                               const float* __restrict__ a_tgt2) {
    int gw = (blockIdx.x * blockDim.x + threadIdx.x) >> 5;
    int lane = threadIdx.x & 31;
    if (gw >= N_NODES) return;
    float w1 = g_Wh2[(size_t)gw * C_OUT + lane];
    float as1 = a_src2[lane], at1 = a_tgt2[lane];
    float w2 = 0.f, as2 = 0.f, at2 = 0.f;
    if (lane + 32 < C_OUT) {
        w2 = g_Wh2[(size_t)gw * C_OUT + lane + 32];
        as2 = a_src2[lane + 32]; at2 = a_tgt2[lane + 32];
    }
    float ss = w1 * as1 + w2 * as2;
    float st = w1 * at1 + w2 * at2;
    #pragma unroll
    for (int o = 16; o > 0; o >>= 1) {
        ss += __shfl_xor_sync(0xFFFFFFFFu, ss, o);
        st += __shfl_xor_sync(0xFFFFFFFFu, st, o);
    }
    if (lane == 0) {
        g_S2src[gw] = ss; g_E2i[gw] = expf(ss); g_F2i[gw] = expf(ALPHA * ss);
        float e = expf(st), f = expf(ALPHA * st);
        __half* pkw = (__half*)&g_pk2[gw >> 1];
        int o = gw & 1;
        pkw[0 + o] = __float2half_rn(st);
        pkw[2 + o] = __float2half_rn(e - f);
        pkw[4 + o] = __float2half_rn(f);
    }
}

// ---------------- launch ----------------
extern "C" void kernel_launch(void* const* d_in, const int* in_sizes, int n_in,
                              void* d_out, int out_size) {
    const float* x      = (const float*)d_in[0];
    const int*   adj    = (const int*)  d_in[1];
    const float* W1     = (const float*)d_in[2];
    const float* a_src1 = (const float*)d_in[3];
    const float* a_tgt1 = (const float*)d_in[4];
    const float* W2     = (const float*)d_in[5];
    const float* a_src2 = (const float*)d_in[6];
    const float* a_tgt2 = (const float*)d_in[7];
    float* out = (float*)d_out;

    pack_adj_kernel<<<(N_NODES * NW * 32) / 256, 256>>>(adj, out, (long)out_size);

    gemm1_kernel<<<dim3((N_NODES + 127) / 128, H1), 256>>>(x, W1);
    scores1_kernel<<<(H1 * N_NODES * 32 + 255) / 256, 256>>>(a_src1, a_tgt1);
    av_mma_kernel<8, 8, false><<<dim3(JP / 128, H1), 128>>>(nullptr);

    gemm2_kernel<<<(N_NODES + 127) / 128, 128>>>(W2);
    scores2_kernel<<<(N_NODES * 32 + 255) / 256, 256>>>(a_src2, a_tgt2);
    av_mma_kernel<5, 6, true><<<dim3(JP / 128, 8), 128>>>(nullptr);
    combine2_kernel<<<(N_NODES * C_OUT + 255) / 256, 256>>>(out);
}

// round 9
// speedup vs baseline: 5.5077x; 1.0146x over previous
#include <cuda_runtime.h>
#include <cuda_fp16.h>
#include <math.h>
#include <stdint.h>

// ---------------- problem constants ----------------
#define N_NODES 6000
#define JP      6016           // N padded to multiple of 64
#define F_IN    512
#define HID     64
#define H1      8
#define C_OUT   40
#define NW      188
#define ALPHA   0.2f
#define OUT_ADJ_OFF (N_NODES * C_OUT)
#define NT_FULL 94             // JP/64

// ---------------- device scratch ----------------
__device__ float    g_Wh  [H1 * N_NODES * HID];
__device__ __half   g_WhT [H1 * HID * (size_t)JP];
__device__ unsigned g_adjb[N_NODES * NW];
__device__ float    g_h1  [N_NODES * (H1 * HID)];
__device__ float    g_Wh2 [N_NODES * C_OUT];
__device__ __half   g_WhT2[HID * (size_t)JP];
__device__ float    g_part[16 * 6016 * 72];      // partials: stride 72; L1 Z@64, L2 Z@40

__device__ float  g_Ei[H1 * N_NODES], g_Fi[H1 * N_NODES];
__device__ float  g_E2i[N_NODES], g_F2i[N_NODES];
// packed per-j tables: entry (j/2) = { e2, f2 } halves; zero in pad region
__device__ uint2  g_pk1[H1 * (JP / 2)];
__device__ uint2  g_pk2[JP / 2];

// ---------------- helpers ----------------
__device__ __forceinline__ uint32_t smem_u32(const void* p) {
    uint32_t a;
    asm("{ .reg .u64 t; cvta.to.shared.u64 t, %1; cvt.u32.u64 %0, t; }" : "=r"(a) : "l"(p));
    return a;
}
__device__ __forceinline__ void mma_16816(float c[4], const uint32_t a[4], const uint32_t b[2]) {
    asm volatile(
        "mma.sync.aligned.m16n8k16.row.col.f32.f16.f16.f32 "
        "{%0,%1,%2,%3}, {%4,%5,%6,%7}, {%8,%9}, {%0,%1,%2,%3};"
        : "+f"(c[0]), "+f"(c[1]), "+f"(c[2]), "+f"(c[3])
        : "r"(a[0]), "r"(a[1]), "r"(a[2]), "r"(a[3]), "r"(b[0]), "r"(b[1]));
}
__device__ __forceinline__ void mma_tf32(float c[4], const uint32_t a[4], const uint32_t b[2]) {
    asm volatile(
        "mma.sync.aligned.m16n8k8.row.col.f32.tf32.tf32.f32 "
        "{%0,%1,%2,%3}, {%4,%5,%6,%7}, {%8,%9}, {%0,%1,%2,%3};"
        : "+f"(c[0]), "+f"(c[1]), "+f"(c[2]), "+f"(c[3])
        : "r"(a[0]), "r"(a[1]), "r"(a[2]), "r"(a[3]), "r"(b[0]), "r"(b[1]));
}
__device__ __forceinline__ void ldsm_x4(uint32_t& r0, uint32_t& r1, uint32_t& r2, uint32_t& r3,
                                        uint32_t addr) {
    asm volatile("ldmatrix.sync.aligned.m8n8.x4.shared.b16 {%0,%1,%2,%3}, [%4];"
                 : "=r"(r0), "=r"(r1), "=r"(r2), "=r"(r3) : "r"(addr));
}
__device__ __forceinline__ uint32_t tf32_of(float x) {
    uint32_t r;
    asm("cvt.rna.tf32.f32 %0, %1;" : "=r"(r) : "f"(x));
    return r;
}
#define CP_ASYNC16(dst, src) \
    asm volatile("cp.async.cg.shared.global [%0], [%1], 16;" :: "r"(dst), "l"(src))
#define CP_COMMIT() asm volatile("cp.async.commit_group;" ::: "memory")
#define CP_WAIT1()  asm volatile("cp.async.wait_group 1;" ::: "memory")
#define CP_WAIT0()  asm volatile("cp.async.wait_group 0;" ::: "memory")

// ---------------- kernel 1: pack adjacency + echo adj to output ----------------
__global__ void pack_adj_kernel(const int* __restrict__ adj,
                                float* __restrict__ outf, long out_size) {
    int gtid = blockIdx.x * blockDim.x + threadIdx.x;
    int warp = gtid >> 5, lane = gtid & 31;
    int row = warp / NW, wj = warp % NW;
    int j = wj * 32 + lane;
    int v = 0;
    if (j < N_NODES) {
        long idx = (long)row * N_NODES + j;
        v = adj[idx];
        long oi = (long)OUT_ADJ_OFF + idx;
        if (oi < out_size) outf[oi] = (float)v;
    }
    unsigned bits = __ballot_sync(0xFFFFFFFFu, v != 0);
    if (lane == 0) g_adjb[row * NW + wj] = bits;
}

// ---------------- kernel 2: Wh = x @ W1[h] on tf32 mma; emits Wh fp32 + WhT fp16 ----------------
__global__ void __launch_bounds__(256) gemm1_kernel(const float* __restrict__ x,
                                                    const float* __restrict__ W1) {
    __shared__ __align__(16) char sbuf[17408];
    float* As = (float*)sbuf;                 // [128][20]
    float* Bs = (float*)(sbuf + 10240);       // [16][72]
    __half* T = (__half*)sbuf;                // [64][136] reused after mainloop

    int h  = blockIdx.y;
    int i0 = blockIdx.x * 128;
    int tid = threadIdx.x;
    int lane = tid & 31, warp = tid >> 5;
    int wr = warp >> 1, wc = warp & 1;
    const float* W1h = W1 + (size_t)h * F_IN * HID;

    float acc[2][4][4];
    #pragma unroll
    for (int m = 0; m < 2; m++)
        #pragma unroll
        for (int n = 0; n < 4; n++)
            #pragma unroll
            for (int c = 0; c < 4; c++) acc[m][n][c] = 0.f;

    int sr = tid >> 1, skk = (tid & 1) * 8;
    int bkk = tid >> 4, bn0 = (tid & 15) * 4;

    for (int k0 = 0; k0 < F_IN; k0 += 16) {
        {
            float4 v0 = make_float4(0.f, 0.f, 0.f, 0.f), v1 = v0;
            if (i0 + sr < N_NODES) {
                const float* src = &x[(size_t)(i0 + sr) * F_IN + k0 + skk];
                v0 = *(const float4*)src;
                v1 = *(const float4*)(src + 4);
            }
            uint32_t* d = (uint32_t*)&As[sr * 20 + skk];
            d[0] = tf32_of(v0.x); d[1] = tf32_of(v0.y); d[2] = tf32_of(v0.z); d[3] = tf32_of(v0.w);
            d[4] = tf32_of(v1.x); d[5] = tf32_of(v1.y); d[6] = tf32_of(v1.z); d[7] = tf32_of(v1.w);
        }
        {
            float4 b = *(const float4*)&W1h[(size_t)(k0 + bkk) * HID + bn0];
            uint32_t* d = (uint32_t*)&Bs[bkk * 72 + bn0];
            d[0] = tf32_of(b.x); d[1] = tf32_of(b.y); d[2] = tf32_of(b.z); d[3] = tf32_of(b.w);
        }
        __syncthreads();

        #pragma unroll
        for (int s = 0; s < 2; s++) {
            int arow = wr * 32 + (lane >> 2);
            int akol = s * 8 + (lane & 3);
            uint32_t af[2][4];
            #pragma unroll
            for (int m = 0; m < 2; m++) {
                int base = (arow + m * 16) * 20 + akol;
                af[m][0] = __float_as_uint(As[base]);
                af[m][1] = __float_as_uint(As[base + 8 * 20]);
                af[m][2] = __float_as_uint(As[base + 4]);
                af[m][3] = __float_as_uint(As[base + 8 * 20 + 4]);
            }
            int bb = (s * 8 + (lane & 3)) * 72 + wc * 32 + (lane >> 2);
            uint32_t bf[4][2];
            #pragma unroll
            for (int n = 0; n < 4; n++) {
                bf[n][0] = __float_as_uint(Bs[bb + n * 8]);
                bf[n][1] = __float_as_uint(Bs[bb + n * 8 + 4 * 72]);
            }
            #pragma unroll
            for (int m = 0; m < 2; m++)
                #pragma unroll
                for (int n = 0; n < 4; n++)
                    mma_tf32(acc[m][n], af[m], bf[n]);
        }
        __syncthreads();
    }

    int rl = wr * 32 + (lane >> 2);
    int cb = wc * 32 + (lane & 3) * 2;
    #pragma unroll
    for (int m = 0; m < 2; m++) {
        int r0 = rl + m * 16, r1 = r0 + 8;
        #pragma unroll
        for (int n = 0; n < 4; n++) {
            int c = cb + n * 8;
            if (i0 + r0 < N_NODES)
                *(float2*)&g_Wh[((size_t)h * N_NODES + i0 + r0) * HID + c] =
                    make_float2(acc[m][n][0], acc[m][n][1]);
            if (i0 + r1 < N_NODES)
                *(float2*)&g_Wh[((size_t)h * N_NODES + i0 + r1) * HID + c] =
                    make_float2(acc[m][n][2], acc[m][n][3]);
            T[(c + 0) * 136 + r0] = __float2half_rn(acc[m][n][0]);
            T[(c + 1) * 136 + r0] = __float2half_rn(acc[m][n][1]);
            T[(c + 0) * 136 + r1] = __float2half_rn(acc[m][n][2]);
            T[(c + 1) * 136 + r1] = __float2half_rn(acc[m][n][3]);
        }
    }
    __syncthreads();
    #pragma unroll
    for (int q = 0; q < 4; q++) {
        int l = tid + 256 * q;               // 0..1023
        int d = l >> 4, o = (l & 15) * 8;
        *(uint4*)&g_WhT[((size_t)h * HID + d) * JP + i0 + o] = *(uint4*)&T[d * 136 + o];
    }
}

// ---------------- kernel 3: per-node scores + packed {e,f} tables (layer 1) ----------------
__global__ void scores1_kernel(const float* __restrict__ a_src,
                               const float* __restrict__ a_tgt) {
    int gw = (blockIdx.x * blockDim.x + threadIdx.x) >> 5;
    int lane = threadIdx.x & 31;
    if (gw >= H1 * N_NODES) return;
    int h = gw / N_NODES, n = gw % N_NODES;
    const float* wh = &g_Wh[((size_t)h * N_NODES + n) * HID];
    float w1 = wh[lane], w2 = wh[lane + 32];
    float ss = w1 * a_src[h * HID + lane] + w2 * a_src[h * HID + lane + 32];
    float st = w1 * a_tgt[h * HID + lane] + w2 * a_tgt[h * HID + lane + 32];
    #pragma unroll
    for (int o = 16; o > 0; o >>= 1) {
        ss += __shfl_xor_sync(0xFFFFFFFFu, ss, o);
        st += __shfl_xor_sync(0xFFFFFFFFu, st, o);
    }
    if (lane == 0) {
        g_Ei[gw] = expf(ss); g_Fi[gw] = expf(ALPHA * ss);
        __half* pk = (__half*)&g_pk1[(size_t)h * (JP / 2) + (n >> 1)];
        int o = n & 1;
        pk[0 + o] = __float2half_rn(expf(st));
        pk[2 + o] = __float2half_rn(expf(ALPHA * st));
    }
}

// ---------------- fused masked-softmax AV on mma.sync ----------------
// 128 threads = 4 warps, 32 rows/warp (2 row-groups) -> 128 rows/block.
// w = mask * max(Ei*ej, Fi*fj)  (exp of leaky-relu via monotone max).
// Triple-buffered cp.async (1 sync/tile); packed {e,f} per-j scalars; partial output.
template<int NG, int NGL, bool L2K>
__global__ void __launch_bounds__(128, 3) av_mma_kernel(float* __restrict__ dummy) {
    __shared__ __align__(16) __half Bbuf[3][64 * 72];
    __shared__ __align__(16) uint2  Pbuf[3][32];

    int tid = threadIdx.x;
    int lane = tid & 31, warp = tid >> 5;
    int i0 = blockIdx.x * 128;

    const float *Eiv, *Fiv;
    const uint2* pk;
    const __half* whT;
    int tbeg, NT, pidx, zcol;
    if (L2K) {
        Eiv = g_E2i; Fiv = g_F2i;
        pk = g_pk2; whT = g_WhT2;
        int y = blockIdx.y;
        tbeg = (y < 6) ? y * 12 : 72 + (y - 6) * 11;
        NT   = (y < 6) ? 12 : 11;
        pidx = y; zcol = 40;
    } else {
        int h = blockIdx.y;
        int hb = h * N_NODES;
        Eiv = g_Ei + hb; Fiv = g_Fi + hb;
        pk = g_pk1 + (size_t)h * (JP / 2);
        whT = g_WhT + (size_t)h * HID * JP;
        tbeg = blockIdx.z * 47; NT = 47;
        pidx = h * 2 + blockIdx.z; zcol = 64;
    }

    // 4 row slots: r0 + {0,8,16,24}
    int r0 = i0 + warp * 32 + (lane >> 2);
    int rowc[4];
    __half2 E2[4], F2[4];
    #pragma unroll
    for (int s = 0; s < 4; s++) {
        rowc[s] = min(r0 + s * 8, N_NODES - 1);
        E2[s] = __half2half2(__float2half_rn(Eiv[rowc[s]]));
        F2[s] = __half2half2(__float2half_rn(Fiv[rowc[s]]));
    }
    int c4 = lane & 3, cb = c4 * 2;

    int nb = (lane & 7) | (((lane >> 4) & 1) << 3);
    int kb = ((lane >> 3) & 1) * 8;
    uint32_t bB[3] = { smem_u32(Bbuf[0]), smem_u32(Bbuf[1]), smem_u32(Bbuf[2]) };
    uint32_t lds_off = (uint32_t)(nb * 72 + kb) * 2;

    float acc[2][NG][4];
    float accz[2][4];
    #pragma unroll
    for (int g = 0; g < 2; g++) {
        #pragma unroll
        for (int n = 0; n < NG; n++)
            #pragma unroll
            for (int c = 0; c < 4; c++) acc[g][n][c] = 0.f;
        #pragma unroll
        for (int c = 0; c < 4; c++) accz[g][c] = 0.f;
    }

    const uint32_t ONES2 = 0x3C003C00u;
    const uint32_t bz[2] = { ONES2, ONES2 };

    auto stage = [&](int t, int b) {
        int j0 = (tbeg + t) * 64;
        #pragma unroll
        for (int i2 = 0; i2 < 4; i2++) {
            int c = tid + 128 * i2;
            int n = c >> 3, o = c & 7;
            CP_ASYNC16(bB[b] + (uint32_t)(n * 144 + o * 16),
                       whT + (size_t)n * JP + j0 + o * 8);
        }
        if (tid >= 96 && tid < 112) {
            int e = tid - 96;                  // 0..15, 2 uint2 entries each
            CP_ASYNC16(smem_u32(&Pbuf[b][e * 2]), pk + (j0 >> 1) + e * 2);
        }
    };

    stage(0, 0); CP_COMMIT();
    if (NT > 1) { stage(1, 1); CP_COMMIT(); }

    uint2 aw_cur[4], aw_nxt[4];
    #pragma unroll
    for (int s = 0; s < 4; s++)
        aw_cur[s] = *(const uint2*)&g_adjb[(size_t)rowc[s] * NW + 2 * tbeg];

    for (int t = 0; t < NT; t++) {
        int b = t % 3;
        if (t + 1 < NT) CP_WAIT1(); else CP_WAIT0();
        __syncthreads();
        if (t + 2 < NT) { stage(t + 2, (t + 2) % 3); CP_COMMIT(); }

        if (t + 1 < NT) {
            #pragma unroll
            for (int s = 0; s < 4; s++)
                aw_nxt[s] = *(const uint2*)&g_adjb[(size_t)rowc[s] * NW + 2 * (tbeg + t + 1)];
        }

        #pragma unroll
        for (int ks = 0; ks < 4; ks++) {
            uint2 p0 = Pbuf[b][ks * 8 + c4];
            uint2 p1 = Pbuf[b][ks * 8 + c4 + 4];
            __half2 eA = *(__half2*)&p0.x, fA = *(__half2*)&p0.y;
            __half2 eB = *(__half2*)&p1.x, fB = *(__half2*)&p1.y;

            // B fragments once, shared by both row groups
            uint32_t bf[NGL][2];
            #pragma unroll
            for (int p = 0; p < NGL / 2; p++)
                ldsm_x4(bf[2 * p][0], bf[2 * p][1], bf[2 * p + 1][0], bf[2 * p + 1][1],
                        bB[b] + lds_off + (uint32_t)(p * 16 * 144 + ks * 32));

            int sh = ((ks & 1) << 4) + cb;
            #pragma unroll
            for (int g = 0; g < 2; g++) {
                uint32_t a[4];
                #pragma unroll
                for (int rr = 0; rr < 2; rr++) {
                    int s = g * 2 + rr;
                    unsigned word = (ks < 2) ? aw_cur[s].x : aw_cur[s].y;
                    unsigned ta = word >> sh;
                    unsigned tb2 = ta >> 8;
                    uint32_t ma = (ta  & 1u) * 0x3C00u + (ta  & 2u) * 0x1E000000u;
                    uint32_t mb = (tb2 & 1u) * 0x3C00u + (tb2 & 2u) * 0x1E000000u;

                    __half2 wa = __hmul2(
                        __hmax2(__hmul2(E2[s], eA), __hmul2(F2[s], fA)), *(__half2*)&ma);
                    __half2 wbv = __hmul2(
                        __hmax2(__hmul2(E2[s], eB), __hmul2(F2[s], fB)), *(__half2*)&mb);

                    a[rr]     = *(uint32_t*)&wa;
                    a[rr + 2] = *(uint32_t*)&wbv;
                }
                #pragma unroll
                for (int n = 0; n < NG; n++)
                    mma_16816(acc[g][n], a, bf[n]);
                mma_16816(accz[g], a, bz);
            }
        }
        #pragma unroll
        for (int s = 0; s < 4; s++) aw_cur[s] = aw_nxt[s];
    }

    // ---- epilogue: partial store (D cols + Z) ----
    #pragma unroll
    for (int g = 0; g < 2; g++) {
        #pragma unroll
        for (int rr = 0; rr < 2; rr++) {
            int row = r0 + (g * 2 + rr) * 8;
            if (row >= N_NODES) continue;
            size_t base = ((size_t)pidx * 6016 + row) * 72;
            #pragma unroll
            for (int n = 0; n < NG; n++)
                *(float2*)&g_part[base + n * 8 + cb] =
                    make_float2(acc[g][n][rr * 2], acc[g][n][rr * 2 + 1]);
            if (cb == 0) g_part[base + zcol] = accz[g][rr * 2];
        }
    }
}

// ---------------- layer-1 combine (2 parts per head): normalize + ELU -> g_h1 ----------------
__global__ void combine1_kernel() {
    int idx = blockIdx.x * blockDim.x + threadIdx.x;   // over H1*N_NODES*32 float2 units
    if (idx >= H1 * N_NODES * 32) return;
    int c2 = idx & 31;
    int rest = idx >> 5;
    int row = rest % N_NODES;
    int h = rest / N_NODES;
    size_t b0 = ((size_t)(h * 2 + 0) * 6016 + row) * 72;
    size_t b1 = ((size_t)(h * 2 + 1) * 6016 + row) * 72;
    float invZ = 1.0f / (g_part[b0 + 64] + g_part[b1 + 64]);
    float2 v0 = *(float2*)&g_part[b0 + c2 * 2];
    float2 v1 = *(float2*)&g_part[b1 + c2 * 2];
    float a = (v0.x + v1.x) * invZ, b = (v0.y + v1.y) * invZ;
    a = a > 0.f ? a : expm1f(a);
    b = b > 0.f ? b : expm1f(b);
    *(float2*)&g_h1[(size_t)row * (H1 * HID) + h * HID + c2 * 2] = make_float2(a, b);
}

// ---------------- layer-2 partial combine (8 parts) ----------------
__global__ void combine2_kernel(float* __restrict__ out) {
    int idx = blockIdx.x * blockDim.x + threadIdx.x;
    if (idx >= N_NODES * C_OUT) return;
    int row = idx / C_OUT, c = idx - row * C_OUT;
    float num = 0.f, z = 0.f;
    #pragma unroll
    for (int y = 0; y < 8; y++) {
        size_t b = ((size_t)y * 6016 + row) * 72;
        num += g_part[b + c];
        z   += g_part[b + 40];
    }
    out[idx] = num / z;
}

// ---------------- kernel 5: Wh2 = h1 @ W2; emits Wh2 fp32 + WhT2 fp16 ----------------
__global__ void __launch_bounds__(128) gemm2_kernel(const float* __restrict__ W2) {
    __shared__ float As[16][128];
    __shared__ float Bs[16 * 40];
    int i0 = blockIdx.x * 128;
    int tid = threadIdx.x;
    int cg = tid & 7, rg = tid >> 3;
    float acc[8][5];
    #pragma unroll
    for (int r = 0; r < 8; r++)
        #pragma unroll
        for (int c = 0; c < 5; c++) acc[r][c] = 0.f;

    for (int k0 = 0; k0 < F_IN; k0 += 16) {
        int r  = tid >> 2;
        int kc = (tid & 3) * 4;
        #pragma unroll
        for (int rr = 0; rr < 4; rr++) {
            int row = r + rr * 32;
            float4 v = make_float4(0.f, 0.f, 0.f, 0.f);
            if (i0 + row < N_NODES)
                v = *(const float4*)&g_h1[(size_t)(i0 + row) * F_IN + k0 + kc];
            As[kc + 0][row] = v.x; As[kc + 1][row] = v.y;
            As[kc + 2][row] = v.z; As[kc + 3][row] = v.w;
        }
        const float* bsrc = W2 + (size_t)k0 * C_OUT;
        #pragma unroll
        for (int i = 0; i < 5; i++) Bs[tid * 5 + i] = bsrc[tid * 5 + i];
        __syncthreads();
        #pragma unroll
        for (int kk = 0; kk < 16; kk++) {
            float a[8], b[5];
            *(float4*)&a[0] = *(float4*)&As[kk][rg * 8];
            *(float4*)&a[4] = *(float4*)&As[kk][rg * 8 + 4];
            #pragma unroll
            for (int i = 0; i < 5; i++) b[i] = Bs[kk * 40 + cg * 5 + i];
            #pragma unroll
            for (int r2 = 0; r2 < 8; r2++)
                #pragma unroll
                for (int c2 = 0; c2 < 5; c2++)
                    acc[r2][c2] += a[r2] * b[c2];
        }
        __syncthreads();
    }
    bool gvalid = (i0 + rg * 8) < N_NODES;
    #pragma unroll
    for (int r = 0; r < 8; r++) {
        int row = i0 + rg * 8 + r;
        if (row < N_NODES) {
            #pragma unroll
            for (int c = 0; c < 5; c++)
                g_Wh2[(size_t)row * C_OUT + cg * 5 + c] = acc[r][c];
        }
    }
    #pragma unroll
    for (int c = 0; c < 5; c++) {
        int col = cg * 5 + c;
        __half tmp[8];
        #pragma unroll
        for (int r2 = 0; r2 < 8; r2++) tmp[r2] = __float2half_rn(acc[r2][c]);
        if (gvalid)
            *(uint4*)&g_WhT2[(size_t)col * JP + i0 + rg * 8] = *(uint4*)tmp;
    }
}

// ---------------- kernel 6: layer-2 scores (packed {e,f} table) ----------------
__global__ void scores2_kernel(const float* __restrict__ a_src2,
                               const float* __restrict__ a_tgt2) {
    int gw = (blockIdx.x * blockDim.x + threadIdx.x) >> 5;
    int lane = threadIdx.x & 31;
    if (gw >= N_NODES) return;
    float w1 = g_Wh2[(size_t)gw * C_OUT + lane];
    float as1 = a_src2[lane], at1 = a_tgt2[lane];
    float w2 = 0.f, as2 = 0.f, at2 = 0.f;
    if (lane + 32 < C_OUT) {
        w2 = g_Wh2[(size_t)gw * C_OUT + lane + 32];
        as2 = a_src2[lane + 32]; at2 = a_tgt2[lane + 32];
    }
    float ss = w1 * as1 + w2 * as2;
    float st = w1 * at1 + w2 * at2;
    #pragma unroll
    for (int o = 16; o > 0; o >>= 1) {
        ss += __shfl_xor_sync(0xFFFFFFFFu, ss, o);
        st += __shfl_xor_sync(0xFFFFFFFFu, st, o);
    }
    if (lane == 0) {
        g_E2i[gw] = expf(ss); g_F2i[gw] = expf(ALPHA * ss);
        __half* pkw = (__half*)&g_pk2[gw >> 1];
        int o = gw & 1;
        pkw[0 + o] = __float2half_rn(expf(st));
        pkw[2 + o] = __float2half_rn(expf(ALPHA * st));
    }
}

// ---------------- launch ----------------
extern "C" void kernel_launch(void* const* d_in, const int* in_sizes, int n_in,
                              void* d_out, int out_size) {
    const float* x      = (const float*)d_in[0];
    const int*   adj    = (const int*)  d_in[1];
    const float* W1     = (const float*)d_in[2];
    const float* a_src1 = (const float*)d_in[3];
    const float* a_tgt1 = (const float*)d_in[4];
    const float* W2     = (const float*)d_in[5];
    const float* a_src2 = (const float*)d_in[6];
    const float* a_tgt2 = (const float*)d_in[7];
    float* out = (float*)d_out;

    pack_adj_kernel<<<(N_NODES * NW * 32) / 256, 256>>>(adj, out, (long)out_size);

    gemm1_kernel<<<dim3((N_NODES + 127) / 128, H1), 256>>>(x, W1);
    scores1_kernel<<<(H1 * N_NODES * 32 + 255) / 256, 256>>>(a_src1, a_tgt1);
    av_mma_kernel<8, 8, false><<<dim3(JP / 128, H1, 2), 128>>>(nullptr);
    combine1_kernel<<<(H1 * N_NODES * 32 + 255) / 256, 256>>>();

    gemm2_kernel<<<(N_NODES + 127) / 128, 128>>>(W2);
    scores2_kernel<<<(N_NODES * 32 + 255) / 256, 256>>>(a_src2, a_tgt2);
    av_mma_kernel<5, 6, true><<<dim3(JP / 128, 8), 128>>>(nullptr);
    combine2_kernel<<<(N_NODES * C_OUT + 255) / 256, 256>>>(out);
}

// round 10
// speedup vs baseline: 5.7004x; 1.0350x over previous
#include <cuda_runtime.h>
#include <cuda_fp16.h>
#include <math.h>
#include <stdint.h>

// ---------------- problem constants ----------------
#define N_NODES 6000
#define JP      6016           // N padded to multiple of 64
#define F_IN    512
#define HID     64
#define H1      8
#define C_OUT   40
#define NW      188
#define ALPHA   0.2f
#define OUT_ADJ_OFF (N_NODES * C_OUT)
#define NT_FULL 94             // JP/64

// ---------------- device scratch ----------------
__device__ float    g_Wh  [H1 * N_NODES * HID];
__device__ __half   g_WhT [H1 * HID * (size_t)JP];
__device__ unsigned g_adjb[N_NODES * NW];
__device__ float    g_h1  [N_NODES * (H1 * HID)];
__device__ float    g_Wh2 [N_NODES * C_OUT];
__device__ __half   g_WhT2[HID * (size_t)JP];
__device__ float    g_part[16 * 6016 * 72];      // partials: stride 72; L1 Z@64, L2 Z@40

__device__ float  g_Ei[H1 * N_NODES], g_Fi[H1 * N_NODES];
__device__ float  g_E2i[N_NODES], g_F2i[N_NODES];
// packed per-j tables: entry (j/2) = { e2, f2 } halves; zero in pad region
__device__ uint2  g_pk1[H1 * (JP / 2)];
__device__ uint2  g_pk2[JP / 2];

// ---------------- helpers ----------------
__device__ __forceinline__ uint32_t smem_u32(const void* p) {
    uint32_t a;
    asm("{ .reg .u64 t; cvta.to.shared.u64 t, %1; cvt.u32.u64 %0, t; }" : "=r"(a) : "l"(p));
    return a;
}
__device__ __forceinline__ void mma_16816(float c[4], const uint32_t a[4], const uint32_t b[2]) {
    asm volatile(
        "mma.sync.aligned.m16n8k16.row.col.f32.f16.f16.f32 "
        "{%0,%1,%2,%3}, {%4,%5,%6,%7}, {%8,%9}, {%0,%1,%2,%3};"
        : "+f"(c[0]), "+f"(c[1]), "+f"(c[2]), "+f"(c[3])
        : "r"(a[0]), "r"(a[1]), "r"(a[2]), "r"(a[3]), "r"(b[0]), "r"(b[1]));
}
__device__ __forceinline__ void mma_tf32(float c[4], const uint32_t a[4], const uint32_t b[2]) {
    asm volatile(
        "mma.sync.aligned.m16n8k8.row.col.f32.tf32.tf32.f32 "
        "{%0,%1,%2,%3}, {%4,%5,%6,%7}, {%8,%9}, {%0,%1,%2,%3};"
        : "+f"(c[0]), "+f"(c[1]), "+f"(c[2]), "+f"(c[3])
        : "r"(a[0]), "r"(a[1]), "r"(a[2]), "r"(a[3]), "r"(b[0]), "r"(b[1]));
}
__device__ __forceinline__ void ldsm_x4(uint32_t& r0, uint32_t& r1, uint32_t& r2, uint32_t& r3,
                                        uint32_t addr) {
    asm volatile("ldmatrix.sync.aligned.m8n8.x4.shared.b16 {%0,%1,%2,%3}, [%4];"
                 : "=r"(r0), "=r"(r1), "=r"(r2), "=r"(r3) : "r"(addr));
}
__device__ __forceinline__ uint32_t tf32_of(float x) {
    uint32_t r;
    asm("cvt.rna.tf32.f32 %0, %1;" : "=r"(r) : "f"(x));
    return r;
}
#define CP_ASYNC16(dst, src) \
    asm volatile("cp.async.cg.shared.global [%0], [%1], 16;" :: "r"(dst), "l"(src))
#define CP_COMMIT() asm volatile("cp.async.commit_group;" ::: "memory")
#define CP_WAIT1()  asm volatile("cp.async.wait_group 1;" ::: "memory")
#define CP_WAIT0()  asm volatile("cp.async.wait_group 0;" ::: "memory")

// ---------------- kernel 1: pack adjacency + echo adj to output ----------------
__global__ void pack_adj_kernel(const int* __restrict__ adj,
                                float* __restrict__ outf, long out_size) {
    int gtid = blockIdx.x * blockDim.x + threadIdx.x;
    int warp = gtid >> 5, lane = gtid & 31;
    int row = warp / NW, wj = warp % NW;
    int j = wj * 32 + lane;
    int v = 0;
    if (j < N_NODES) {
        long idx = (long)row * N_NODES + j;
        v = adj[idx];
        long oi = (long)OUT_ADJ_OFF + idx;
        if (oi < out_size) outf[oi] = (float)v;
    }
    unsigned bits = __ballot_sync(0xFFFFFFFFu, v != 0);
    if (lane == 0) g_adjb[row * NW + wj] = bits;
}

// ---------------- tf32 GEMM template: C[128 x 64] = A[128 x 512] * B (N cols, padded 64) ----------------
// 256 threads = 8 warps (4 row-groups x 2 col-groups). Emits fp32 C + fp16 transposed C.
template<int NB>  // valid B cols (64 for layer1, 40 for layer2)
__device__ __forceinline__ void gemm_tf32_body(
    const float* __restrict__ Asrc,  // [N_NODES][512] row-major (base already offset)
    const float* __restrict__ Bsrc,  // [512][NB] row-major
    float* __restrict__ Cout,        // [N_NODES][NB] fp32
    __half* __restrict__ CtT,        // [64][JP] fp16 transposed
    int i0)
{
    __shared__ __align__(16) char sbuf[17408];
    float* As = (float*)sbuf;                 // [128][20]
    float* Bs = (float*)(sbuf + 10240);       // [16][72]
    __half* T = (__half*)sbuf;                // [64][136] reused after mainloop

    int tid = threadIdx.x;
    int lane = tid & 31, warp = tid >> 5;
    int wr = warp >> 1, wc = warp & 1;

    float acc[2][4][4];
    #pragma unroll
    for (int m = 0; m < 2; m++)
        #pragma unroll
        for (int n = 0; n < 4; n++)
            #pragma unroll
            for (int c = 0; c < 4; c++) acc[m][n][c] = 0.f;

    int sr = tid >> 1, skk = (tid & 1) * 8;
    int bkk = tid >> 4, bn0 = (tid & 15) * 4;

    for (int k0 = 0; k0 < F_IN; k0 += 16) {
        {
            float4 v0 = make_float4(0.f, 0.f, 0.f, 0.f), v1 = v0;
            if (i0 + sr < N_NODES) {
                const float* src = &Asrc[(size_t)(i0 + sr) * F_IN + k0 + skk];
                v0 = *(const float4*)src;
                v1 = *(const float4*)(src + 4);
            }
            uint32_t* d = (uint32_t*)&As[sr * 20 + skk];
            d[0] = tf32_of(v0.x); d[1] = tf32_of(v0.y); d[2] = tf32_of(v0.z); d[3] = tf32_of(v0.w);
            d[4] = tf32_of(v1.x); d[5] = tf32_of(v1.y); d[6] = tf32_of(v1.z); d[7] = tf32_of(v1.w);
        }
        {
            float4 b = make_float4(0.f, 0.f, 0.f, 0.f);
            if (bn0 < NB)
                b = *(const float4*)&Bsrc[(size_t)(k0 + bkk) * NB + bn0];
            uint32_t* d = (uint32_t*)&Bs[bkk * 72 + bn0];
            d[0] = tf32_of(b.x); d[1] = tf32_of(b.y); d[2] = tf32_of(b.z); d[3] = tf32_of(b.w);
        }
        __syncthreads();

        #pragma unroll
        for (int s = 0; s < 2; s++) {
            int arow = wr * 32 + (lane >> 2);
            int akol = s * 8 + (lane & 3);
            uint32_t af[2][4];
            #pragma unroll
            for (int m = 0; m < 2; m++) {
                int base = (arow + m * 16) * 20 + akol;
                af[m][0] = __float_as_uint(As[base]);
                af[m][1] = __float_as_uint(As[base + 8 * 20]);
                af[m][2] = __float_as_uint(As[base + 4]);
                af[m][3] = __float_as_uint(As[base + 8 * 20 + 4]);
            }
            int bb = (s * 8 + (lane & 3)) * 72 + wc * 32 + (lane >> 2);
            uint32_t bf[4][2];
            #pragma unroll
            for (int n = 0; n < 4; n++) {
                bf[n][0] = __float_as_uint(Bs[bb + n * 8]);
                bf[n][1] = __float_as_uint(Bs[bb + n * 8 + 4 * 72]);
            }
            #pragma unroll
            for (int m = 0; m < 2; m++)
                #pragma unroll
                for (int n = 0; n < 4; n++)
                    mma_tf32(acc[m][n], af[m], bf[n]);
        }
        __syncthreads();
    }

    int rl = wr * 32 + (lane >> 2);
    int cbx = wc * 32 + (lane & 3) * 2;
    #pragma unroll
    for (int m = 0; m < 2; m++) {
        int r0 = rl + m * 16, r1 = r0 + 8;
        #pragma unroll
        for (int n = 0; n < 4; n++) {
            int c = cbx + n * 8;
            if (c < NB) {
                if (i0 + r0 < N_NODES)
                    *(float2*)&Cout[(size_t)(i0 + r0) * NB + c] =
                        make_float2(acc[m][n][0], acc[m][n][1]);
                if (i0 + r1 < N_NODES)
                    *(float2*)&Cout[(size_t)(i0 + r1) * NB + c] =
                        make_float2(acc[m][n][2], acc[m][n][3]);
            }
            T[(c + 0) * 136 + r0] = __float2half_rn(acc[m][n][0]);
            T[(c + 1) * 136 + r0] = __float2half_rn(acc[m][n][1]);
            T[(c + 0) * 136 + r1] = __float2half_rn(acc[m][n][2]);
            T[(c + 1) * 136 + r1] = __float2half_rn(acc[m][n][3]);
        }
    }
    __syncthreads();
    #pragma unroll
    for (int q = 0; q < 4; q++) {
        int l = tid + 256 * q;               // 0..1023
        int d = l >> 4, o = (l & 15) * 8;
        *(uint4*)&CtT[(size_t)d * JP + i0 + o] = *(uint4*)&T[d * 136 + o];
    }
}

__global__ void __launch_bounds__(256) gemm1_kernel(const float* __restrict__ x,
                                                    const float* __restrict__ W1) {
    int h = blockIdx.y;
    gemm_tf32_body<HID>(x, W1 + (size_t)h * F_IN * HID,
                        g_Wh + (size_t)h * N_NODES * HID,
                        g_WhT + (size_t)h * HID * JP,
                        blockIdx.x * 128);
}

__global__ void __launch_bounds__(256) gemm2_kernel(const float* __restrict__ W2) {
    gemm_tf32_body<C_OUT>(g_h1, W2, g_Wh2, g_WhT2, blockIdx.x * 128);
}

// ---------------- kernel 3: per-node scores + packed {e,f} tables (layer 1) ----------------
__global__ void scores1_kernel(const float* __restrict__ a_src,
                               const float* __restrict__ a_tgt) {
    int gw = (blockIdx.x * blockDim.x + threadIdx.x) >> 5;
    int lane = threadIdx.x & 31;
    if (gw >= H1 * N_NODES) return;
    int h = gw / N_NODES, n = gw % N_NODES;
    const float* wh = &g_Wh[((size_t)h * N_NODES + n) * HID];
    float w1 = wh[lane], w2 = wh[lane + 32];
    float ss = w1 * a_src[h * HID + lane] + w2 * a_src[h * HID + lane + 32];
    float st = w1 * a_tgt[h * HID + lane] + w2 * a_tgt[h * HID + lane + 32];
    #pragma unroll
    for (int o = 16; o > 0; o >>= 1) {
        ss += __shfl_xor_sync(0xFFFFFFFFu, ss, o);
        st += __shfl_xor_sync(0xFFFFFFFFu, st, o);
    }
    if (lane == 0) {
        g_Ei[gw] = expf(ss); g_Fi[gw] = expf(ALPHA * ss);
        __half* pk = (__half*)&g_pk1[(size_t)h * (JP / 2) + (n >> 1)];
        int o = n & 1;
        pk[0 + o] = __float2half_rn(expf(st));
        pk[2 + o] = __float2half_rn(expf(ALPHA * st));
    }
}

// ---------------- fused masked-softmax AV on mma.sync ----------------
// 128 threads = 4 warps, 32 rows/warp (2 row-groups) -> 128 rows/block.
// w = mask * max(Ei*ej, Fi*fj). Register-lean: A-frags built first, B-frags
// consumed 4-regs-at-a-time; no adjacency prefetch (L2-resident).
template<int NG, int NGL, bool L2K>
__global__ void __launch_bounds__(128, 4) av_mma_kernel(float* __restrict__ dummy) {
    __shared__ __align__(16) __half Bbuf[3][64 * 72];
    __shared__ __align__(16) uint2  Pbuf[3][32];

    int tid = threadIdx.x;
    int lane = tid & 31, warp = tid >> 5;
    int i0 = blockIdx.x * 128;

    const float *Eiv, *Fiv;
    const uint2* pk;
    const __half* whT;
    int tbeg, NT, pidx, zcol;
    if (L2K) {
        Eiv = g_E2i; Fiv = g_F2i;
        pk = g_pk2; whT = g_WhT2;
        int y = blockIdx.y;
        tbeg = (y < 6) ? y * 12 : 72 + (y - 6) * 11;
        NT   = (y < 6) ? 12 : 11;
        pidx = y; zcol = 40;
    } else {
        int h = blockIdx.y;
        int hb = h * N_NODES;
        Eiv = g_Ei + hb; Fiv = g_Fi + hb;
        pk = g_pk1 + (size_t)h * (JP / 2);
        whT = g_WhT + (size_t)h * HID * JP;
        tbeg = blockIdx.z * 47; NT = 47;
        pidx = h * 2 + blockIdx.z; zcol = 64;
    }

    // 4 row slots: r0 + {0,8,16,24}
    int r0 = i0 + warp * 32 + (lane >> 2);
    int rowc[4];
    __half2 E2[4], F2[4];
    #pragma unroll
    for (int s = 0; s < 4; s++) {
        rowc[s] = min(r0 + s * 8, N_NODES - 1);
        E2[s] = __half2half2(__float2half_rn(Eiv[rowc[s]]));
        F2[s] = __half2half2(__float2half_rn(Fiv[rowc[s]]));
    }
    int c4 = lane & 3, cb = c4 * 2;

    int nb = (lane & 7) | (((lane >> 4) & 1) << 3);
    int kb = ((lane >> 3) & 1) * 8;
    uint32_t bB[3] = { smem_u32(Bbuf[0]), smem_u32(Bbuf[1]), smem_u32(Bbuf[2]) };
    uint32_t lds_off = (uint32_t)(nb * 72 + kb) * 2;

    float acc[2][NG][4];
    float accz[2][4];
    #pragma unroll
    for (int g = 0; g < 2; g++) {
        #pragma unroll
        for (int n = 0; n < NG; n++)
            #pragma unroll
            for (int c = 0; c < 4; c++) acc[g][n][c] = 0.f;
        #pragma unroll
        for (int c = 0; c < 4; c++) accz[g][c] = 0.f;
    }

    const uint32_t ONES2 = 0x3C003C00u;
    const uint32_t bz[2] = { ONES2, ONES2 };

    auto stage = [&](int t, int b) {
        int j0 = (tbeg + t) * 64;
        #pragma unroll
        for (int i2 = 0; i2 < 4; i2++) {
            int c = tid + 128 * i2;
            int n = c >> 3, o = c & 7;
            CP_ASYNC16(bB[b] + (uint32_t)(n * 144 + o * 16),
                       whT + (size_t)n * JP + j0 + o * 8);
        }
        if (tid >= 96 && tid < 112) {
            int e = tid - 96;                  // 0..15, 2 uint2 entries each
            CP_ASYNC16(smem_u32(&Pbuf[b][e * 2]), pk + (j0 >> 1) + e * 2);
        }
    };

    stage(0, 0); CP_COMMIT();
    if (NT > 1) { stage(1, 1); CP_COMMIT(); }

    for (int t = 0; t < NT; t++) {
        int b = t % 3;
        if (t + 1 < NT) CP_WAIT1(); else CP_WAIT0();
        __syncthreads();
        if (t + 2 < NT) { stage(t + 2, (t + 2) % 3); CP_COMMIT(); }

        // adjacency words for this tile (L2-resident, latency covered by occupancy)
        uint2 aw[4];
        #pragma unroll
        for (int s = 0; s < 4; s++)
            aw[s] = *(const uint2*)&g_adjb[(size_t)rowc[s] * NW + 2 * (tbeg + t)];

        #pragma unroll
        for (int ks = 0; ks < 4; ks++) {
            uint2 p0 = Pbuf[b][ks * 8 + c4];
            uint2 p1 = Pbuf[b][ks * 8 + c4 + 4];
            __half2 eA = *(__half2*)&p0.x, fA = *(__half2*)&p0.y;
            __half2 eB = *(__half2*)&p1.x, fB = *(__half2*)&p1.y;

            int sh = ((ks & 1) << 4) + cb;
            // build A fragments for BOTH row groups first (8 regs)
            uint32_t a2[2][4];
            #pragma unroll
            for (int g = 0; g < 2; g++) {
                #pragma unroll
                for (int rr = 0; rr < 2; rr++) {
                    int s = g * 2 + rr;
                    unsigned word = (ks < 2) ? aw[s].x : aw[s].y;
                    unsigned ta = word >> sh;
                    unsigned tb2 = ta >> 8;
                    uint32_t ma = (ta  & 1u) * 0x3C00u + (ta  & 2u) * 0x1E000000u;
                    uint32_t mb = (tb2 & 1u) * 0x3C00u + (tb2 & 2u) * 0x1E000000u;

                    __half2 wa = __hmul2(
                        __hmax2(__hmul2(E2[s], eA), __hmul2(F2[s], fA)), *(__half2*)&ma);
                    __half2 wbv = __hmul2(
                        __hmax2(__hmul2(E2[s], eB), __hmul2(F2[s], fB)), *(__half2*)&mb);

                    a2[g][rr]     = *(uint32_t*)&wa;
                    a2[g][rr + 2] = *(uint32_t*)&wbv;
                }
            }
            // consume B fragments 4 regs at a time
            #pragma unroll
            for (int p = 0; p < NGL / 2; p++) {
                uint32_t bf0[2], bf1[2];
                ldsm_x4(bf0[0], bf0[1], bf1[0], bf1[1],
                        bB[b] + lds_off + (uint32_t)(p * 16 * 144 + ks * 32));
                int n0 = 2 * p, n1 = 2 * p + 1;
                if (n0 < NG) { mma_16816(acc[0][n0], a2[0], bf0); mma_16816(acc[1][n0], a2[1], bf0); }
                if (n1 < NG) { mma_16816(acc[0][n1], a2[0], bf1); mma_16816(acc[1][n1], a2[1], bf1); }
            }
            mma_16816(accz[0], a2[0], bz);
            mma_16816(accz[1], a2[1], bz);
        }
    }

    // ---- epilogue: partial store (D cols + Z) ----
    #pragma unroll
    for (int g = 0; g < 2; g++) {
        #pragma unroll
        for (int rr = 0; rr < 2; rr++) {
            int row = r0 + (g * 2 + rr) * 8;
            if (row >= N_NODES) continue;
            size_t base = ((size_t)pidx * 6016 + row) * 72;
            #pragma unroll
            for (int n = 0; n < NG; n++)
                *(float2*)&g_part[base + n * 8 + cb] =
                    make_float2(acc[g][n][rr * 2], acc[g][n][rr * 2 + 1]);
            if (cb == 0) g_part[base + zcol] = accz[g][rr * 2];
        }
    }
}

// ---------------- layer-1 combine (2 parts per head): normalize + ELU -> g_h1 ----------------
__global__ void combine1_kernel() {
    int idx = blockIdx.x * blockDim.x + threadIdx.x;   // over H1*N_NODES*32 float2 units
    if (idx >= H1 * N_NODES * 32) return;
    int c2 = idx & 31;
    int rest = idx >> 5;
    int row = rest % N_NODES;
    int h = rest / N_NODES;
    size_t b0 = ((size_t)(h * 2 + 0) * 6016 + row) * 72;
    size_t b1 = ((size_t)(h * 2 + 1) * 6016 + row) * 72;
    float invZ = 1.0f / (g_part[b0 + 64] + g_part[b1 + 64]);
    float2 v0 = *(float2*)&g_part[b0 + c2 * 2];
    float2 v1 = *(float2*)&g_part[b1 + c2 * 2];
    float a = (v0.x + v1.x) * invZ, b = (v0.y + v1.y) * invZ;
    a = a > 0.f ? a : expm1f(a);
    b = b > 0.f ? b : expm1f(b);
    *(float2*)&g_h1[(size_t)row * (H1 * HID) + h * HID + c2 * 2] = make_float2(a, b);
}

// ---------------- layer-2 partial combine (8 parts) ----------------
__global__ void combine2_kernel(float* __restrict__ out) {
    int idx = blockIdx.x * blockDim.x + threadIdx.x;
    if (idx >= N_NODES * C_OUT) return;
    int row = idx / C_OUT, c = idx - row * C_OUT;
    float num = 0.f, z = 0.f;
    #pragma unroll
    for (int y = 0; y < 8; y++) {
        size_t b = ((size_t)y * 6016 + row) * 72;
        num += g_part[b + c];
        z   += g_part[b + 40];
    }
    out[idx] = num / z;
}

// ---------------- kernel 6: layer-2 scores (packed {e,f} table) ----------------
__global__ void scores2_kernel(const float* __restrict__ a_src2,
                               const float* __restrict__ a_tgt2) {
    int gw = (blockIdx.x * blockDim.x + threadIdx.x) >> 5;
    int lane = threadIdx.x & 31;
    if (gw >= N_NODES) return;
    float w1 = g_Wh2[(size_t)gw * C_OUT + lane];
    float as1 = a_src2[lane], at1 = a_tgt2[lane];
    float w2 = 0.f, as2 = 0.f, at2 = 0.f;
    if (lane + 32 < C_OUT) {
        w2 = g_Wh2[(size_t)gw * C_OUT + lane + 32];
        as2 = a_src2[lane + 32]; at2 = a_tgt2[lane + 32];
    }
    float ss = w1 * as1 + w2 * as2;
    float st = w1 * at1 + w2 * at2;
    #pragma unroll
    for (int o = 16; o > 0; o >>= 1) {
        ss += __shfl_xor_sync(0xFFFFFFFFu, ss, o);
        st += __shfl_xor_sync(0xFFFFFFFFu, st, o);
    }
    if (lane == 0) {
        g_E2i[gw] = expf(ss); g_F2i[gw] = expf(ALPHA * ss);
        __half* pkw = (__half*)&g_pk2[gw >> 1];
        int o = gw & 1;
        pkw[0 + o] = __float2half_rn(expf(st));
        pkw[2 + o] = __float2half_rn(expf(ALPHA * st));
    }
}

// ---------------- launch ----------------
extern "C" void kernel_launch(void* const* d_in, const int* in_sizes, int n_in,
                              void* d_out, int out_size) {
    const float* x      = (const float*)d_in[0];
    const int*   adj    = (const int*)  d_in[1];
    const float* W1     = (const float*)d_in[2];
    const float* a_src1 = (const float*)d_in[3];
    const float* a_tgt1 = (const float*)d_in[4];
    const float* W2     = (const float*)d_in[5];
    const float* a_src2 = (const float*)d_in[6];
    const float* a_tgt2 = (const float*)d_in[7];
    float* out = (float*)d_out;

    pack_adj_kernel<<<(N_NODES * NW * 32) / 256, 256>>>(adj, out, (long)out_size);

    gemm1_kernel<<<dim3((N_NODES + 127) / 128, H1), 256>>>(x, W1);
    scores1_kernel<<<(H1 * N_NODES * 32 + 255) / 256, 256>>>(a_src1, a_tgt1);
    av_mma_kernel<8, 8, false><<<dim3(JP / 128, H1, 2), 128>>>(nullptr);
    combine1_kernel<<<(H1 * N_NODES * 32 + 255) / 256, 256>>>();

    gemm2_kernel<<<(N_NODES + 127) / 128, 256>>>(W2);
    scores2_kernel<<<(N_NODES * 32 + 255) / 256, 256>>>(a_src2, a_tgt2);
    av_mma_kernel<5, 6, true><<<dim3(JP / 128, 8), 128>>>(nullptr);
    combine2_kernel<<<(N_NODES * C_OUT + 255) / 256, 256>>>(out);
}

// round 12
// speedup vs baseline: 5.8735x; 1.0303x over previous
#include <cuda_runtime.h>
#include <cuda_fp16.h>
#include <math.h>
#include <stdint.h>

// ---------------- problem constants ----------------
#define N_NODES 6000
#define JP      6016           // N padded to multiple of 64
#define F_IN    512
#define HID     64
#define H1      8
#define C_OUT   40
#define NW      188
#define ALPHA   0.2f
#define OUT_ADJ_OFF (N_NODES * C_OUT)
#define NT_FULL 94             // JP/64

// ---------------- device scratch ----------------
__device__ float    g_Wh  [H1 * N_NODES * HID];
__device__ __half   g_WhT [H1 * HID * (size_t)JP];
__device__ unsigned g_adjb[N_NODES * NW];
__device__ float    g_h1  [N_NODES * (H1 * HID)];
__device__ float    g_Wh2 [N_NODES * C_OUT];
__device__ __half   g_WhT2[HID * (size_t)JP];
__device__ float    g_part[32 * 6016 * 72];      // partials: stride 72; L1 Z@64, L2 Z@40

__device__ float  g_Ei[H1 * N_NODES], g_Fi[H1 * N_NODES];
__device__ float  g_E2i[N_NODES], g_F2i[N_NODES];
// packed per-j tables: entry (j/2) = { e2, f2 } halves; zero in pad region
__device__ uint2  g_pk1[H1 * (JP / 2)];
__device__ uint2  g_pk2[JP / 2];

// ---------------- helpers ----------------
__device__ __forceinline__ uint32_t smem_u32(const void* p) {
    uint32_t a;
    asm("{ .reg .u64 t; cvta.to.shared.u64 t, %1; cvt.u32.u64 %0, t; }" : "=r"(a) : "l"(p));
    return a;
}
__device__ __forceinline__ void mma_16816(float c[4], const uint32_t a[4], const uint32_t b[2]) {
    asm volatile(
        "mma.sync.aligned.m16n8k16.row.col.f32.f16.f16.f32 "
        "{%0,%1,%2,%3}, {%4,%5,%6,%7}, {%8,%9}, {%0,%1,%2,%3};"
        : "+f"(c[0]), "+f"(c[1]), "+f"(c[2]), "+f"(c[3])
        : "r"(a[0]), "r"(a[1]), "r"(a[2]), "r"(a[3]), "r"(b[0]), "r"(b[1]));
}
__device__ __forceinline__ void mma_tf32(float c[4], const uint32_t a[4], const uint32_t b[2]) {
    asm volatile(
        "mma.sync.aligned.m16n8k8.row.col.f32.tf32.tf32.f32 "
        "{%0,%1,%2,%3}, {%4,%5,%6,%7}, {%8,%9}, {%0,%1,%2,%3};"
        : "+f"(c[0]), "+f"(c[1]), "+f"(c[2]), "+f"(c[3])
        : "r"(a[0]), "r"(a[1]), "r"(a[2]), "r"(a[3]), "r"(b[0]), "r"(b[1]));
}
__device__ __forceinline__ void ldsm_x4(uint32_t& r0, uint32_t& r1, uint32_t& r2, uint32_t& r3,
                                        uint32_t addr) {
    asm volatile("ldmatrix.sync.aligned.m8n8.x4.shared.b16 {%0,%1,%2,%3}, [%4];"
                 : "=r"(r0), "=r"(r1), "=r"(r2), "=r"(r3) : "r"(addr));
}
__device__ __forceinline__ uint32_t tf32_of(float x) {
    uint32_t r;
    asm("cvt.rna.tf32.f32 %0, %1;" : "=r"(r) : "f"(x));
    return r;
}
#define CP_ASYNC16(dst, src) \
    asm volatile("cp.async.cg.shared.global [%0], [%1], 16;" :: "r"(dst), "l"(src))
#define CP_COMMIT() asm volatile("cp.async.commit_group;" ::: "memory")
#define CP_WAIT1()  asm volatile("cp.async.wait_group 1;" ::: "memory")
#define CP_WAIT0()  asm volatile("cp.async.wait_group 0;" ::: "memory")

// ---------------- kernel 1: pack adjacency + echo adj to output ----------------
__global__ void pack_adj_kernel(const int* __restrict__ adj,
                                float* __restrict__ outf, long out_size) {
    int gtid = blockIdx.x * blockDim.x + threadIdx.x;
    int warp = gtid >> 5, lane = gtid & 31;
    int row = warp / NW, wj = warp % NW;
    int j = wj * 32 + lane;
    int v = 0;
    if (j < N_NODES) {
        long idx = (long)row * N_NODES + j;
        v = adj[idx];
        long oi = (long)OUT_ADJ_OFF + idx;
        if (oi < out_size) outf[oi] = (float)v;
    }
    unsigned bits = __ballot_sync(0xFFFFFFFFu, v != 0);
    if (lane == 0) g_adjb[row * NW + wj] = bits;
}

// ---------------- tf32 GEMM template: C[128 x 64] = A[128 x 512] * B (N cols, padded 64) ----------------
template<int NB>  // valid B cols (64 for layer1, 40 for layer2)
__device__ __forceinline__ void gemm_tf32_body(
    const float* __restrict__ Asrc,
    const float* __restrict__ Bsrc,
    float* __restrict__ Cout,
    __half* __restrict__ CtT,
    int i0)
{
    __shared__ __align__(16) char sbuf[17408];
    float* As = (float*)sbuf;                 // [128][20]
    float* Bs = (float*)(sbuf + 10240);       // [16][72]
    __half* T = (__half*)sbuf;                // [64][136] reused after mainloop

    int tid = threadIdx.x;
    int lane = tid & 31, warp = tid >> 5;
    int wr = warp >> 1, wc = warp & 1;

    float acc[2][4][4];
    #pragma unroll
    for (int m = 0; m < 2; m++)
        #pragma unroll
        for (int n = 0; n < 4; n++)
            #pragma unroll
            for (int c = 0; c < 4; c++) acc[m][n][c] = 0.f;

    int sr = tid >> 1, skk = (tid & 1) * 8;
    int bkk = tid >> 4, bn0 = (tid & 15) * 4;

    for (int k0 = 0; k0 < F_IN; k0 += 16) {
        {
            float4 v0 = make_float4(0.f, 0.f, 0.f, 0.f), v1 = v0;
            if (i0 + sr < N_NODES) {
                const float* src = &Asrc[(size_t)(i0 + sr) * F_IN + k0 + skk];
                v0 = *(const float4*)src;
                v1 = *(const float4*)(src + 4);
            }
            uint32_t* d = (uint32_t*)&As[sr * 20 + skk];
            d[0] = tf32_of(v0.x); d[1] = tf32_of(v0.y); d[2] = tf32_of(v0.z); d[3] = tf32_of(v0.w);
            d[4] = tf32_of(v1.x); d[5] = tf32_of(v1.y); d[6] = tf32_of(v1.z); d[7] = tf32_of(v1.w);
        }
        {
            float4 b = make_float4(0.f, 0.f, 0.f, 0.f);
            if (bn0 < NB)
                b = *(const float4*)&Bsrc[(size_t)(k0 + bkk) * NB + bn0];
            uint32_t* d = (uint32_t*)&Bs[bkk * 72 + bn0];
            d[0] = tf32_of(b.x); d[1] = tf32_of(b.y); d[2] = tf32_of(b.z); d[3] = tf32_of(b.w);
        }
        __syncthreads();

        #pragma unroll
        for (int s = 0; s < 2; s++) {
            int arow = wr * 32 + (lane >> 2);
            int akol = s * 8 + (lane & 3);
            uint32_t af[2][4];
            #pragma unroll
            for (int m = 0; m < 2; m++) {
                int base = (arow + m * 16) * 20 + akol;
                af[m][0] = __float_as_uint(As[base]);
                af[m][1] = __float_as_uint(As[base + 8 * 20]);
                af[m][2] = __float_as_uint(As[base + 4]);
                af[m][3] = __float_as_uint(As[base + 8 * 20 + 4]);
            }
            int bb = (s * 8 + (lane & 3)) * 72 + wc * 32 + (lane >> 2);
            uint32_t bf[4][2];
            #pragma unroll
            for (int n = 0; n < 4; n++) {
                bf[n][0] = __float_as_uint(Bs[bb + n * 8]);
                bf[n][1] = __float_as_uint(Bs[bb + n * 8 + 4 * 72]);
            }
            #pragma unroll
            for (int m = 0; m < 2; m++)
                #pragma unroll
                for (int n = 0; n < 4; n++)
                    mma_tf32(acc[m][n], af[m], bf[n]);
        }
        __syncthreads();
    }

    int rl = wr * 32 + (lane >> 2);
    int cbx = wc * 32 + (lane & 3) * 2;
    #pragma unroll
    for (int m = 0; m < 2; m++) {
        int r0 = rl + m * 16, r1 = r0 + 8;
        #pragma unroll
        for (int n = 0; n < 4; n++) {
            int c = cbx + n * 8;
            if (c < NB) {
                if (i0 + r0 < N_NODES)
                    *(float2*)&Cout[(size_t)(i0 + r0) * NB + c] =
                        make_float2(acc[m][n][0], acc[m][n][1]);
                if (i0 + r1 < N_NODES)
                    *(float2*)&Cout[(size_t)(i0 + r1) * NB + c] =
                        make_float2(acc[m][n][2], acc[m][n][3]);
            }
            T[(c + 0) * 136 + r0] = __float2half_rn(acc[m][n][0]);
            T[(c + 1) * 136 + r0] = __float2half_rn(acc[m][n][1]);
            T[(c + 0) * 136 + r1] = __float2half_rn(acc[m][n][2]);
            T[(c + 1) * 136 + r1] = __float2half_rn(acc[m][n][3]);
        }
    }
    __syncthreads();
    #pragma unroll
    for (int q = 0; q < 4; q++) {
        int l = tid + 256 * q;               // 0..1023
        int d = l >> 4, o = (l & 15) * 8;
        *(uint4*)&CtT[(size_t)d * JP + i0 + o] = *(uint4*)&T[d * 136 + o];
    }
}

__global__ void __launch_bounds__(256) gemm1_kernel(const float* __restrict__ x,
                                                    const float* __restrict__ W1) {
    int h = blockIdx.y;
    gemm_tf32_body<HID>(x, W1 + (size_t)h * F_IN * HID,
                        g_Wh + (size_t)h * N_NODES * HID,
                        g_WhT + (size_t)h * HID * JP,
                        blockIdx.x * 128);
}

__global__ void __launch_bounds__(256) gemm2_kernel(const float* __restrict__ W2) {
    gemm_tf32_body<C_OUT>(g_h1, W2, g_Wh2, g_WhT2, blockIdx.x * 128);
}

// ---------------- kernel 3: per-node scores + packed {e,f} tables (layer 1) ----------------
__global__ void scores1_kernel(const float* __restrict__ a_src,
                               const float* __restrict__ a_tgt) {
    int gw = (blockIdx.x * blockDim.x + threadIdx.x) >> 5;
    int lane = threadIdx.x & 31;
    if (gw >= H1 * N_NODES) return;
    int h = gw / N_NODES, n = gw % N_NODES;
    const float* wh = &g_Wh[((size_t)h * N_NODES + n) * HID];
    float w1 = wh[lane], w2 = wh[lane + 32];
    float ss = w1 * a_src[h * HID + lane] + w2 * a_src[h * HID + lane + 32];
    float st = w1 * a_tgt[h * HID + lane] + w2 * a_tgt[h * HID + lane + 32];
    #pragma unroll
    for (int o = 16; o > 0; o >>= 1) {
        ss += __shfl_xor_sync(0xFFFFFFFFu, ss, o);
        st += __shfl_xor_sync(0xFFFFFFFFu, st, o);
    }
    if (lane == 0) {
        g_Ei[gw] = expf(ss); g_Fi[gw] = expf(ALPHA * ss);
        __half* pk = (__half*)&g_pk1[(size_t)h * (JP / 2) + (n >> 1)];
        int o = n & 1;
        pk[0 + o] = __float2half_rn(expf(st));
        pk[2 + o] = __float2half_rn(expf(ALPHA * st));
    }
}

// ---------------- fused masked-softmax AV on mma.sync ----------------
// 128 threads = 4 warps, 32 rows/warp (2 row-groups) -> 128 rows/block.
// w = mask * max(Ei*ej, Fi*fj). L1: j split 4-ways (wave-quantization fix).
template<int NG, int NGL, bool L2K>
__global__ void __launch_bounds__(128, 4) av_mma_kernel(float* __restrict__ dummy) {
    __shared__ __align__(16) __half Bbuf[3][64 * 72];
    __shared__ __align__(16) uint2  Pbuf[3][32];

    int tid = threadIdx.x;
    int lane = tid & 31, warp = tid >> 5;
    int i0 = blockIdx.x * 128;

    const float *Eiv, *Fiv;
    const uint2* pk;
    const __half* whT;
    int tbeg, NT, pidx, zcol;
    if (L2K) {
        Eiv = g_E2i; Fiv = g_F2i;
        pk = g_pk2; whT = g_WhT2;
        int y = blockIdx.y;
        tbeg = (y < 6) ? y * 12 : 72 + (y - 6) * 11;
        NT   = (y < 6) ? 12 : 11;
        pidx = y; zcol = 40;
    } else {
        int h = blockIdx.y;
        int hb = h * N_NODES;
        Eiv = g_Ei + hb; Fiv = g_Fi + hb;
        pk = g_pk1 + (size_t)h * (JP / 2);
        whT = g_WhT + (size_t)h * HID * JP;
        int z = blockIdx.z;                    // 4-way j split: 24,24,23,23
        tbeg = (z < 2) ? z * 24 : 48 + (z - 2) * 23;
        NT   = (z < 2) ? 24 : 23;
        pidx = h * 4 + z; zcol = 64;
    }

    // 4 row slots: r0 + {0,8,16,24}
    int r0 = i0 + warp * 32 + (lane >> 2);
    int rowc[4];
    __half2 E2[4], F2[4];
    #pragma unroll
    for (int s = 0; s < 4; s++) {
        rowc[s] = min(r0 + s * 8, N_NODES - 1);
        E2[s] = __half2half2(__float2half_rn(Eiv[rowc[s]]));
        F2[s] = __half2half2(__float2half_rn(Fiv[rowc[s]]));
    }
    int c4 = lane & 3, cb = c4 * 2;

    int nb = (lane & 7) | (((lane >> 4) & 1) << 3);
    int kb = ((lane >> 3) & 1) * 8;
    uint32_t bB[3] = { smem_u32(Bbuf[0]), smem_u32(Bbuf[1]), smem_u32(Bbuf[2]) };
    uint32_t lds_off = (uint32_t)(nb * 72 + kb) * 2;

    float acc[2][NG][4];
    float accz[2][4];
    #pragma unroll
    for (int g = 0; g < 2; g++) {
        #pragma unroll
        for (int n = 0; n < NG; n++)
            #pragma unroll
            for (int c = 0; c < 4; c++) acc[g][n][c] = 0.f;
        #pragma unroll
        for (int c = 0; c < 4; c++) accz[g][c] = 0.f;
    }

    const uint32_t ONES2 = 0x3C003C00u;
    const uint32_t bz[2] = { ONES2, ONES2 };

    auto stage = [&](int t, int b) {
        int j0 = (tbeg + t) * 64;
        #pragma unroll
        for (int i2 = 0; i2 < 4; i2++) {
            int c = tid + 128 * i2;
            int n = c >> 3, o = c & 7;
            CP_ASYNC16(bB[b] + (uint32_t)(n * 144 + o * 16),
                       whT + (size_t)n * JP + j0 + o * 8);
        }
        if (tid >= 96 && tid < 112) {
            int e = tid - 96;                  // 0..15, 2 uint2 entries each
            CP_ASYNC16(smem_u32(&Pbuf[b][e * 2]), pk + (j0 >> 1) + e * 2);
        }
    };

    stage(0, 0); CP_COMMIT();
    if (NT > 1) { stage(1, 1); CP_COMMIT(); }

    for (int t = 0; t < NT; t++) {
        int b = t % 3;
        if (t + 1 < NT) CP_WAIT1(); else CP_WAIT0();
        __syncthreads();
        if (t + 2 < NT) { stage(t + 2, (t + 2) % 3); CP_COMMIT(); }

        // adjacency words for this tile (L2-resident, latency covered by occupancy)
        uint2 aw[4];
        #pragma unroll
        for (int s = 0; s < 4; s++)
            aw[s] = *(const uint2*)&g_adjb[(size_t)rowc[s] * NW + 2 * (tbeg + t)];

        #pragma unroll
        for (int ks = 0; ks < 4; ks++) {
            uint2 p0 = Pbuf[b][ks * 8 + c4];
            uint2 p1 = Pbuf[b][ks * 8 + c4 + 4];
            __half2 eA = *(__half2*)&p0.x, fA = *(__half2*)&p0.y;
            __half2 eB = *(__half2*)&p1.x, fB = *(__half2*)&p1.y;

            int sh = ((ks & 1) << 4) + cb;
            // build A fragments for BOTH row groups first (8 regs)
            uint32_t a2[2][4];
            #pragma unroll
            for (int g = 0; g < 2; g++) {
                #pragma unroll
                for (int rr = 0; rr < 2; rr++) {
                    int s = g * 2 + rr;
                    unsigned word = (ks < 2) ? aw[s].x : aw[s].y;
                    unsigned ta = word >> sh;
                    unsigned tb2 = ta >> 8;
                    uint32_t ma = (ta  & 1u) * 0x3C00u + (ta  & 2u) * 0x1E000000u;
                    uint32_t mb = (tb2 & 1u) * 0x3C00u + (tb2 & 2u) * 0x1E000000u;

                    __half2 wa = __hmul2(
                        __hmax2(__hmul2(E2[s], eA), __hmul2(F2[s], fA)), *(__half2*)&ma);
                    __half2 wbv = __hmul2(
                        __hmax2(__hmul2(E2[s], eB), __hmul2(F2[s], fB)), *(__half2*)&mb);

                    a2[g][rr]     = *(uint32_t*)&wa;
                    a2[g][rr + 2] = *(uint32_t*)&wbv;
                }
            }
            // consume B fragments 4 regs at a time
            #pragma unroll
            for (int p = 0; p < NGL / 2; p++) {
                uint32_t bf0[2], bf1[2];
                ldsm_x4(bf0[0], bf0[1], bf1[0], bf1[1],
                        bB[b] + lds_off + (uint32_t)(p * 16 * 144 + ks * 32));
                int n0 = 2 * p, n1 = 2 * p + 1;
                if (n0 < NG) { mma_16816(acc[0][n0], a2[0], bf0); mma_16816(acc[1][n0], a2[1], bf0); }
                if (n1 < NG) { mma_16816(acc[0][n1], a2[0], bf1); mma_16816(acc[1][n1], a2[1], bf1); }
            }
            mma_16816(accz[0], a2[0], bz);
            mma_16816(accz[1], a2[1], bz);
        }
    }

    // ---- epilogue: partial store (D cols + Z) ----
    #pragma unroll
    for (int g = 0; g < 2; g++) {
        #pragma unroll
        for (int rr = 0; rr < 2; rr++) {
            int row = r0 + (g * 2 + rr) * 8;
            if (row >= N_NODES) continue;
            size_t base = ((size_t)pidx * 6016 + row) * 72;
            #pragma unroll
            for (int n = 0; n < NG; n++)
                *(float2*)&g_part[base + n * 8 + cb] =
                    make_float2(acc[g][n][rr * 2], acc[g][n][rr * 2 + 1]);
            if (cb == 0) g_part[base + zcol] = accz[g][rr * 2];
        }
    }
}

// ---------------- layer-1 combine (4 parts per head): normalize + ELU -> g_h1 ----------------
__global__ void combine1_kernel() {
    int idx = blockIdx.x * blockDim.x + threadIdx.x;   // over H1*N_NODES*32 float2 units
    if (idx >= H1 * N_NODES * 32) return;
    int c2 = idx & 31;
    int rest = idx >> 5;
    int row = rest % N_NODES;
    int h = rest / N_NODES;
    float na = 0.f, nb2 = 0.f, z = 0.f;
    #pragma unroll
    for (int k = 0; k < 4; k++) {
        size_t b = ((size_t)(h * 4 + k) * 6016 + row) * 72;
        float2 v = *(float2*)&g_part[b + c2 * 2];
        na += v.x; nb2 += v.y;
        z += g_part[b + 64];
    }
    float invZ = 1.0f / z;
    float a = na * invZ, b = nb2 * invZ;
    a = a > 0.f ? a : expm1f(a);
    b = b > 0.f ? b : expm1f(b);
    *(float2*)&g_h1[(size_t)row * (H1 * HID) + h * HID + c2 * 2] = make_float2(a, b);
}

// ---------------- layer-2 partial combine (8 parts) ----------------
__global__ void combine2_kernel(float* __restrict__ out) {
    int idx = blockIdx.x * blockDim.x + threadIdx.x;
    if (idx >= N_NODES * C_OUT) return;
    int row = idx / C_OUT, c = idx - row * C_OUT;
    float num = 0.f, z = 0.f;
    #pragma unroll
    for (int y = 0; y < 8; y++) {
        size_t b = ((size_t)y * 6016 + row) * 72;
        num += g_part[b + c];
        z   += g_part[b + 40];
    }
    out[idx] = num / z;
}

// ---------------- kernel 6: layer-2 scores (packed {e,f} table) ----------------
__global__ void scores2_kernel(const float* __restrict__ a_src2,
                               const float* __restrict__ a_tgt2) {
    int gw = (blockIdx.x * blockDim.x + threadIdx.x) >> 5;
    int lane = threadIdx.x & 31;
    if (gw >= N_NODES) return;
    float w1 = g_Wh2[(size_t)gw * C_OUT + lane];
    float as1 = a_src2[lane], at1 = a_tgt2[lane];
    float w2 = 0.f, as2 = 0.f, at2 = 0.f;
    if (lane + 32 < C_OUT) {
        w2 = g_Wh2[(size_t)gw * C_OUT + lane + 32];
        as2 = a_src2[lane + 32]; at2 = a_tgt2[lane + 32];
    }
    float ss = w1 * as1 + w2 * as2;
    float st = w1 * at1 + w2 * at2;
    #pragma unroll
    for (int o = 16; o > 0; o >>= 1) {
        ss += __shfl_xor_sync(0xFFFFFFFFu, ss, o);
        st += __shfl_xor_sync(0xFFFFFFFFu, st, o);
    }
    if (lane == 0) {
        g_E2i[gw] = expf(ss); g_F2i[gw] = expf(ALPHA * ss);
        __half* pkw = (__half*)&g_pk2[gw >> 1];
        int o = gw & 1;
        pkw[0 + o] = __float2half_rn(expf(st));
        pkw[2 + o] = __float2half_rn(expf(ALPHA * st));
    }
}

// ---------------- launch ----------------
extern "C" void kernel_launch(void* const* d_in, const int* in_sizes, int n_in,
                              void* d_out, int out_size) {
    const float* x      = (const float*)d_in[0];
    const int*   adj    = (const int*)  d_in[1];
    const float* W1     = (const float*)d_in[2];
    const float* a_src1 = (const float*)d_in[3];
    const float* a_tgt1 = (const float*)d_in[4];
    const float* W2     = (const float*)d_in[5];
    const float* a_src2 = (const float*)d_in[6];
    const float* a_tgt2 = (const float*)d_in[7];
    float* out = (float*)d_out;

    pack_adj_kernel<<<(N_NODES * NW * 32) / 256, 256>>>(adj, out, (long)out_size);

    gemm1_kernel<<<dim3((N_NODES + 127) / 128, H1), 256>>>(x, W1);
    scores1_kernel<<<(H1 * N_NODES * 32 + 255) / 256, 256>>>(a_src1, a_tgt1);
    av_mma_kernel<8, 8, false><<<dim3(JP / 128, H1, 4), 128>>>(nullptr);
    combine1_kernel<<<(H1 * N_NODES * 32 + 255) / 256, 256>>>();

    gemm2_kernel<<<(N_NODES + 127) / 128, 256>>>(W2);
    scores2_kernel<<<(N_NODES * 32 + 255) / 256, 256>>>(a_src2, a_tgt2);
    av_mma_kernel<5, 6, true><<<dim3(JP / 128, 8), 128>>>(nullptr);
    combine2_kernel<<<(N_NODES * C_OUT + 255) / 256, 256>>>(out);
}